// round 6
// baseline (speedup 1.0000x reference)
#include <cuda_runtime.h>
#include <cuda_bf16.h>
#include <cuda_fp16.h>
#include <cstdint>

#define NB   8
#define SEQ  2048
#define ED   1024
#define HD   64

__device__ float g_q[NB * SEQ * HD];
__device__ float g_k[NB * SEQ * HD];
__device__ float g_v[NB * SEQ * HD];
__device__ uint32_t g_whp[192 * 512];   // W hi, bf16 pairs packed
__device__ uint32_t g_wlp[192 * 512];   // W lo

// ---------------- helpers ----------------
__device__ __forceinline__ void mma_bf16(float* d, const uint32_t* a, const uint32_t* b) {
    asm("mma.sync.aligned.m16n8k16.row.col.f32.bf16.bf16.f32 "
        "{%0,%1,%2,%3}, {%4,%5,%6,%7}, {%8,%9}, {%0,%1,%2,%3};"
        : "+f"(d[0]), "+f"(d[1]), "+f"(d[2]), "+f"(d[3])
        : "r"(a[0]), "r"(a[1]), "r"(a[2]), "r"(a[3]), "r"(b[0]), "r"(b[1]));
}
__device__ __forceinline__ void mma_f16(float* d, const uint32_t* a, const uint32_t* b) {
    asm("mma.sync.aligned.m16n8k16.row.col.f32.f16.f16.f32 "
        "{%0,%1,%2,%3}, {%4,%5,%6,%7}, {%8,%9}, {%0,%1,%2,%3};"
        : "+f"(d[0]), "+f"(d[1]), "+f"(d[2]), "+f"(d[3])
        : "r"(a[0]), "r"(a[1]), "r"(a[2]), "r"(a[3]), "r"(b[0]), "r"(b[1]));
}
__device__ __forceinline__ uint32_t packh2(float a, float b) {
    __half2 h = __floats2half2_rn(a, b);
    return *(uint32_t*)&h;
}
// split (a,b) into packed bf16 hi pair + lo pair (lo = residual)
__device__ __forceinline__ void split2(float a, float b, uint32_t& hi, uint32_t& lo) {
    __nv_bfloat162 h2 = __floats2bfloat162_rn(a, b);
    float ar = a - __bfloat162float(h2.x);
    float br = b - __bfloat162float(h2.y);
    __nv_bfloat162 l2 = __floats2bfloat162_rn(ar, br);
    hi = *(uint32_t*)&h2;
    lo = *(uint32_t*)&l2;
}
// split (a,b) into packed fp16 hi pair + residual pair
__device__ __forceinline__ void split2h(float a, float b, uint32_t& hi, uint32_t& lo) {
    __half2 h2 = __floats2half2_rn(a, b);
    float ar = a - __half2float(__low2half(h2));
    float br = b - __half2float(__high2half(h2));
    __half2 l2 = __floats2half2_rn(ar, br);
    hi = *(uint32_t*)&h2;
    lo = *(uint32_t*)&l2;
}

// ---------------------------------------------------------------------------
// Prep: split W (q|k|v stacked, 192 x 1024) into packed bf16 hi/lo pairs.
// ---------------------------------------------------------------------------
__global__ void prep_w(const float* __restrict__ Wq, const float* __restrict__ Wk,
                       const float* __restrict__ Wv)
{
    int idx = blockIdx.x * 256 + threadIdx.x;
    if (idx >= 192 * 512) return;
    int row = idx >> 9;
    int pc  = idx & 511;
    const float* src = (row < 64)  ? Wq + (size_t)row * ED
                     : (row < 128) ? Wk + (size_t)(row - 64) * ED
                                   : Wv + (size_t)(row - 128) * ED;
    float a = src[pc * 2], b = src[pc * 2 + 1];
    uint32_t h, l;
    split2(a, b, h, l);
    g_whp[idx] = h;
    g_wlp[idx] = l;
}

// ---------------------------------------------------------------------------
// QKV via bf16 m16n8k16, 3-term split (xh*wh + xh*wl + xl*wh ~ fp32 accuracy).
// BM=64, N=192, K-chunk 32 (2 ksteps). 256 CTAs x 8 warps (2m x 4n), 2 CTAs/SM.
// ---------------------------------------------------------------------------
__global__ __launch_bounds__(256, 2)
void qkv_kernel(const float* __restrict__ x,
                const float* __restrict__ bq, const float* __restrict__ bk,
                const float* __restrict__ bv)
{
    __shared__ uint32_t xs_h[64][20],  xs_l[64][20];
    __shared__ uint32_t ws_h[192][20], ws_l[192][20];

    const int t    = threadIdx.x;
    const int lane = t & 31;
    const int wid  = t >> 5;
    const int wm   = wid & 1;
    const int wn   = wid >> 1;
    const int gq   = lane >> 2;
    const int tg   = lane & 3;
    const size_t rowBase = (size_t)blockIdx.x * 64;

    float acc[2][6][4];
    #pragma unroll
    for (int mi = 0; mi < 2; mi++)
        #pragma unroll
        for (int ni = 0; ni < 6; ni++)
            #pragma unroll
            for (int j = 0; j < 4; j++) acc[mi][ni][j] = 0.f;

    const int xr = t >> 2;
    const int xc = (t & 3) * 8;

    for (int ch = 0; ch < 32; ch++) {
        __syncthreads();
        {
            const float* xp = x + (rowBase + xr) * ED + ch * 32 + xc;
            float4 f0 = *(const float4*)xp;
            float4 f1 = *(const float4*)(xp + 4);
            uint4 hv, lv;
            split2(f0.x, f0.y, hv.x, lv.x);
            split2(f0.z, f0.w, hv.y, lv.y);
            split2(f1.x, f1.y, hv.z, lv.z);
            split2(f1.z, f1.w, hv.w, lv.w);
            *(uint4*)&xs_h[xr][(t & 3) * 4] = hv;
            *(uint4*)&xs_l[xr][(t & 3) * 4] = lv;
        }
        #pragma unroll
        for (int i = 0; i < 3; i++) {
            int slot = t + i * 256;
            int r = slot >> 2, c4 = (slot & 3) * 4;
            *(uint4*)&ws_h[r][c4] = *(const uint4*)&g_whp[r * 512 + ch * 16 + c4];
            *(uint4*)&ws_l[r][c4] = *(const uint4*)&g_wlp[r * 512 + ch * 16 + c4];
        }
        __syncthreads();

        #pragma unroll
        for (int kk = 0; kk < 2; kk++) {
            const int c0 = kk * 8 + tg;
            uint32_t ah[2][4], al[2][4];
            #pragma unroll
            for (int mi = 0; mi < 2; mi++) {
                int r0 = wm * 32 + mi * 16 + gq;
                ah[mi][0] = xs_h[r0][c0];     ah[mi][1] = xs_h[r0 + 8][c0];
                ah[mi][2] = xs_h[r0][c0 + 4]; ah[mi][3] = xs_h[r0 + 8][c0 + 4];
                al[mi][0] = xs_l[r0][c0];     al[mi][1] = xs_l[r0 + 8][c0];
                al[mi][2] = xs_l[r0][c0 + 4]; al[mi][3] = xs_l[r0 + 8][c0 + 4];
            }
            uint32_t bh[6][2], bl[6][2];
            #pragma unroll
            for (int ni = 0; ni < 6; ni++) {
                int n0 = wn * 48 + ni * 8 + gq;
                bh[ni][0] = ws_h[n0][c0]; bh[ni][1] = ws_h[n0][c0 + 4];
                bl[ni][0] = ws_l[n0][c0]; bl[ni][1] = ws_l[n0][c0 + 4];
            }
            #pragma unroll
            for (int mi = 0; mi < 2; mi++)
                #pragma unroll
                for (int ni = 0; ni < 6; ni++) mma_bf16(acc[mi][ni], ah[mi], bh[ni]);
            #pragma unroll
            for (int mi = 0; mi < 2; mi++)
                #pragma unroll
                for (int ni = 0; ni < 6; ni++) mma_bf16(acc[mi][ni], ah[mi], bl[ni]);
            #pragma unroll
            for (int mi = 0; mi < 2; mi++)
                #pragma unroll
                for (int ni = 0; ni < 6; ni++) mma_bf16(acc[mi][ni], al[mi], bh[ni]);
        }
    }

    #pragma unroll
    for (int ni = 0; ni < 6; ni++) {
        const int gc0 = wn * 48 + ni * 8;
        const int wi  = gc0 >> 6;
        const int h0  = (gc0 & 63) + tg * 2;
        float* outp      = (wi == 0) ? g_q : (wi == 1) ? g_k : g_v;
        const float* bp  = (wi == 0) ? bq  : (wi == 1) ? bk  : bv;
        const float b0 = bp[h0], b1 = bp[h0 + 1];
        #pragma unroll
        for (int mi = 0; mi < 2; mi++) {
            size_t r = rowBase + wm * 32 + mi * 16 + gq;
            float2 v0 = make_float2(acc[mi][ni][0] + b0, acc[mi][ni][1] + b1);
            *(float2*)(outp + r * HD + h0) = v0;
            float2 v1 = make_float2(acc[mi][ni][2] + b0, acc[mi][ni][3] + b1);
            *(float2*)(outp + (r + 8) * HD + h0) = v1;
        }
    }
}

// ---------------------------------------------------------------------------
// Causal flash attention, fp16 m16n8k16 MMA (q 2-split, k/P/V single fp16 =
// tf32-equivalent accuracy). 8 warps in 2 independent groups (named barriers),
// group g owns 32-row k-tiles 2*iter+g. 2 CTAs/SM.
// smem: kst[g][32 krows][36 u32] (K h-pairs), vt[g][64 h][20 u32] (V^T
// krow-pairs); merge overlay reuses the same buffer.
// ---------------------------------------------------------------------------
#define GROUP_BAR(gid) asm volatile("bar.sync %0, 128;" :: "r"((gid) + 1) : "memory")

__global__ __launch_bounds__(256, 2)
void attn_kernel(float* __restrict__ out)
{
    __shared__ __align__(16) uint32_t sbuf[4864];

    const int t    = threadIdx.x;
    const int lane = t & 31;
    const int w    = t >> 5;
    const int g    = w >> 2;
    const int wg   = w & 3;
    const int gq   = lane >> 2;
    const int tg   = lane & 3;
    const int tl   = t & 127;
    const int b    = blockIdx.y;
    const size_t bOff = (size_t)b * SEQ * HD;

    uint32_t* kst = sbuf + g * 1152;          // [32][36]
    uint32_t* vt  = sbuf + 2304 + g * 1280;   // [64][20]
    float* obuf = (float*)sbuf;               // merge overlay [64][68]
    float* mlb  = (float*)(sbuf + 4352);      // merge overlay m,l

    // loader mappings
    const int klr  = tl >> 2;          // K: row 0..31
    const int klc  = tl & 3;           // K: 16-float col block
    const int vlc  = tl >> 3;          // V: h quad 0..15
    const int vlr4 = (tl & 7) * 4;     // V: 4-row base

    for (int pass = 0; pass < 2; pass++) {
        __syncthreads();               // merge overlay safe before reuse
        const int qt = pass ? (31 - blockIdx.x) : blockIdx.x;
        const int qbase = qt * 64;
        const int r0l = wg * 16 + gq;

        // Q fragments (fp16 2-term split), straight from gmem
        uint32_t qh2[4][4], ql2[4][4];
        {
            const float* qp = g_q + bOff + (size_t)(qbase + r0l) * HD;
            #pragma unroll
            for (int c = 0; c < 4; c++) {
                int c0 = c * 16 + tg * 2;
                float2 f00 = *(const float2*)(qp + c0);
                float2 f10 = *(const float2*)(qp + 8 * HD + c0);
                float2 f01 = *(const float2*)(qp + c0 + 8);
                float2 f11 = *(const float2*)(qp + 8 * HD + c0 + 8);
                split2h(f00.x, f00.y, qh2[c][0], ql2[c][0]);
                split2h(f10.x, f10.y, qh2[c][1], ql2[c][1]);
                split2h(f01.x, f01.y, qh2[c][2], ql2[c][2]);
                split2h(f11.x, f11.y, qh2[c][3], ql2[c][3]);
            }
        }

        float m0 = -1e30f, m1 = -1e30f, l0 = 0.f, l1 = 0.f;
        float O[8][4];
        #pragma unroll
        for (int nh = 0; nh < 8; nh++)
            #pragma unroll
            for (int j = 0; j < 4; j++) O[nh][j] = 0.f;

        for (int iter = 0; iter <= qt; iter++) {
            const int kbase = (2 * iter + g) * 32;
            GROUP_BAR(g);   // group done reading previous tile
            // ---- K tile -> packed fp16 pairs [krow][hpair] ----
            {
                const float* kp = g_k + bOff + (size_t)(kbase + klr) * HD + klc * 16;
                uint32_t pr[8];
                #pragma unroll
                for (int q4 = 0; q4 < 4; q4++) {
                    float4 f = *(const float4*)(kp + q4 * 4);
                    pr[q4 * 2]     = packh2(f.x, f.y);
                    pr[q4 * 2 + 1] = packh2(f.z, f.w);
                }
                uint32_t* dst = kst + klr * 36 + klc * 8;
                *(uint4*)dst       = make_uint4(pr[0], pr[1], pr[2], pr[3]);
                *(uint4*)(dst + 4) = make_uint4(pr[4], pr[5], pr[6], pr[7]);
            }
            // ---- V tile -> transposed packed pairs [h][krow-pair] ----
            {
                const float* vp = g_v + bOff + (size_t)(kbase + vlr4) * HD + vlc * 4;
                float4 v0 = *(const float4*)vp;
                float4 v1 = *(const float4*)(vp + HD);
                float4 v2 = *(const float4*)(vp + 2 * HD);
                float4 v3 = *(const float4*)(vp + 3 * HD);
                uint32_t* base = vt + (vlc * 4) * 20 + (vlr4 >> 1);
                *(uint2*)(base)      = make_uint2(packh2(v0.x, v1.x), packh2(v2.x, v3.x));
                *(uint2*)(base + 20) = make_uint2(packh2(v0.y, v1.y), packh2(v2.y, v3.y));
                *(uint2*)(base + 40) = make_uint2(packh2(v0.z, v1.z), packh2(v2.z, v3.z));
                *(uint2*)(base + 60) = make_uint2(packh2(v0.w, v1.w), packh2(v2.w, v3.w));
            }
            GROUP_BAR(g);   // tile visible

            // ---- S = Q K^T  (qh*k + ql*k, fp16 k16) ----
            float s[4][4];
            #pragma unroll
            for (int nk = 0; nk < 4; nk++)
                #pragma unroll
                for (int j = 0; j < 4; j++) s[nk][j] = 0.f;

            #pragma unroll
            for (int c = 0; c < 4; c++) {
                uint32_t bfr[4][2];
                #pragma unroll
                for (int nk = 0; nk < 4; nk++) {
                    const uint32_t* kr = kst + (nk * 8 + gq) * 36 + c * 8 + tg;
                    bfr[nk][0] = kr[0];
                    bfr[nk][1] = kr[4];
                }
                #pragma unroll
                for (int nk = 0; nk < 4; nk++) mma_f16(s[nk], qh2[c], bfr[nk]);
                #pragma unroll
                for (int nk = 0; nk < 4; nk++) mma_f16(s[nk], ql2[c], bfr[nk]);
            }

            // ---- scale + causal mask ----
            const float sc = 0.125f;
            if (iter == qt) {
                const int row0 = qbase + r0l, row1 = row0 + 8;
                #pragma unroll
                for (int nk = 0; nk < 4; nk++) {
                    int c = kbase + nk * 8 + tg * 2;
                    s[nk][0] = (c     > row0) ? -1e30f : s[nk][0] * sc;
                    s[nk][1] = (c + 1 > row0) ? -1e30f : s[nk][1] * sc;
                    s[nk][2] = (c     > row1) ? -1e30f : s[nk][2] * sc;
                    s[nk][3] = (c + 1 > row1) ? -1e30f : s[nk][3] * sc;
                }
            } else {
                #pragma unroll
                for (int nk = 0; nk < 4; nk++)
                    #pragma unroll
                    for (int j = 0; j < 4; j++) s[nk][j] *= sc;
            }

            // ---- online softmax ----
            float rm0 = -1e30f, rm1 = -1e30f;
            #pragma unroll
            for (int nk = 0; nk < 4; nk++) {
                rm0 = fmaxf(rm0, fmaxf(s[nk][0], s[nk][1]));
                rm1 = fmaxf(rm1, fmaxf(s[nk][2], s[nk][3]));
            }
            rm0 = fmaxf(rm0, __shfl_xor_sync(0xffffffffu, rm0, 1));
            rm0 = fmaxf(rm0, __shfl_xor_sync(0xffffffffu, rm0, 2));
            rm1 = fmaxf(rm1, __shfl_xor_sync(0xffffffffu, rm1, 1));
            rm1 = fmaxf(rm1, __shfl_xor_sync(0xffffffffu, rm1, 2));

            float mn0 = fmaxf(m0, rm0), mn1 = fmaxf(m1, rm1);
            float a0 = __expf(m0 - mn0), a1 = __expf(m1 - mn1);
            m0 = mn0; m1 = mn1;

            float rs0 = 0.f, rs1 = 0.f;
            #pragma unroll
            for (int nk = 0; nk < 4; nk++) {
                s[nk][0] = __expf(s[nk][0] - mn0); rs0 += s[nk][0];
                s[nk][1] = __expf(s[nk][1] - mn0); rs0 += s[nk][1];
                s[nk][2] = __expf(s[nk][2] - mn1); rs1 += s[nk][2];
                s[nk][3] = __expf(s[nk][3] - mn1); rs1 += s[nk][3];
            }
            rs0 += __shfl_xor_sync(0xffffffffu, rs0, 1);
            rs0 += __shfl_xor_sync(0xffffffffu, rs0, 2);
            rs1 += __shfl_xor_sync(0xffffffffu, rs1, 1);
            rs1 += __shfl_xor_sync(0xffffffffu, rs1, 2);
            l0 = l0 * a0 + rs0;
            l1 = l1 * a1 + rs1;
            #pragma unroll
            for (int nh = 0; nh < 8; nh++) {
                O[nh][0] *= a0; O[nh][1] *= a0;
                O[nh][2] *= a1; O[nh][3] *= a1;
            }

            // ---- O += P V  (P packed in-place from C-frag; V^T pairs) ----
            #pragma unroll
            for (int c = 0; c < 2; c++) {
                uint32_t pa[4];
                pa[0] = packh2(s[2 * c][0],     s[2 * c][1]);
                pa[1] = packh2(s[2 * c][2],     s[2 * c][3]);
                pa[2] = packh2(s[2 * c + 1][0], s[2 * c + 1][1]);
                pa[3] = packh2(s[2 * c + 1][2], s[2 * c + 1][3]);
                #pragma unroll
                for (int nh = 0; nh < 8; nh++) {
                    const uint32_t* vr = vt + (nh * 8 + gq) * 20 + c * 8 + tg;
                    uint32_t vb[2];
                    vb[0] = vr[0];
                    vb[1] = vr[4];
                    mma_f16(O[nh], pa, vb);
                }
            }
        }

        // ---- merge the two groups ----
        __syncthreads();
        if (g == 1) {
            mlb[r0l * 2]           = m0;
            mlb[r0l * 2 + 1]       = l0;
            mlb[(r0l + 8) * 2]     = m1;
            mlb[(r0l + 8) * 2 + 1] = l1;
            #pragma unroll
            for (int nh = 0; nh < 8; nh++) {
                int c = nh * 8 + tg * 2;
                *(float2*)&obuf[r0l * 68 + c]       = make_float2(O[nh][0], O[nh][1]);
                *(float2*)&obuf[(r0l + 8) * 68 + c] = make_float2(O[nh][2], O[nh][3]);
            }
        }
        __syncthreads();
        if (g == 0) {
            float mb0 = mlb[r0l * 2],       lb0 = mlb[r0l * 2 + 1];
            float mb1 = mlb[(r0l + 8) * 2], lb1 = mlb[(r0l + 8) * 2 + 1];
            float mm0 = fmaxf(m0, mb0), mm1 = fmaxf(m1, mb1);
            float ea0 = __expf(m0 - mm0),  eb0 = __expf(mb0 - mm0);
            float ea1 = __expf(m1 - mm1),  eb1 = __expf(mb1 - mm1);
            float inv0 = 1.f / (ea0 * l0 + eb0 * lb0);
            float inv1 = 1.f / (ea1 * l1 + eb1 * lb1);
            const int r = qbase + r0l;
            #pragma unroll
            for (int nh = 0; nh < 8; nh++) {
                int c = nh * 8 + tg * 2;
                float2 ob0 = *(float2*)&obuf[r0l * 68 + c];
                float2 ob1 = *(float2*)&obuf[(r0l + 8) * 68 + c];
                float2 v0 = make_float2((ea0 * O[nh][0] + eb0 * ob0.x) * inv0,
                                        (ea0 * O[nh][1] + eb0 * ob0.y) * inv0);
                float2 v1 = make_float2((ea1 * O[nh][2] + eb1 * ob1.x) * inv1,
                                        (ea1 * O[nh][3] + eb1 * ob1.y) * inv1);
                *(float2*)(out + bOff + (size_t)r * HD + c)       = v0;
                *(float2*)(out + bOff + (size_t)(r + 8) * HD + c) = v1;
            }
        }
    }
}

// ---------------------------------------------------------------------------
extern "C" void kernel_launch(void* const* d_in, const int* in_sizes, int n_in,
                              void* d_out, int out_size)
{
    const float* x  = (const float*)d_in[0];
    const float* Wq = (const float*)d_in[1];
    const float* bq = (const float*)d_in[2];
    const float* Wk = (const float*)d_in[3];
    const float* bk = (const float*)d_in[4];
    const float* Wv = (const float*)d_in[5];
    const float* bv = (const float*)d_in[6];
    float* out = (float*)d_out;

    prep_w<<<384, 256>>>(Wq, Wk, Wv);
    qkv_kernel<<<(NB * SEQ) / 64, 256>>>(x, bq, bk, bv);
    attn_kernel<<<dim3(16, NB), 256>>>(out);
}

// round 7
// speedup vs baseline: 1.0339x; 1.0339x over previous
#include <cuda_runtime.h>
#include <cuda_bf16.h>
#include <cuda_fp16.h>
#include <cstdint>

#define NB   8
#define SEQ  2048
#define ED   1024
#define HD   64

__device__ float g_q[NB * SEQ * HD];
__device__ float g_k[NB * SEQ * HD];
__device__ float g_v[NB * SEQ * HD];
__device__ uint32_t g_whp[192 * 512];
__device__ uint32_t g_wlp[192 * 512];

// ---------------- helpers ----------------
__device__ __forceinline__ void mma_bf16(float* d, const uint32_t* a, const uint32_t* b) {
    asm("mma.sync.aligned.m16n8k16.row.col.f32.bf16.bf16.f32 "
        "{%0,%1,%2,%3}, {%4,%5,%6,%7}, {%8,%9}, {%0,%1,%2,%3};"
        : "+f"(d[0]), "+f"(d[1]), "+f"(d[2]), "+f"(d[3])
        : "r"(a[0]), "r"(a[1]), "r"(a[2]), "r"(a[3]), "r"(b[0]), "r"(b[1]));
}
__device__ __forceinline__ void mma_f16(float* d, const uint32_t* a, const uint32_t* b) {
    asm("mma.sync.aligned.m16n8k16.row.col.f32.f16.f16.f32 "
        "{%0,%1,%2,%3}, {%4,%5,%6,%7}, {%8,%9}, {%0,%1,%2,%3};"
        : "+f"(d[0]), "+f"(d[1]), "+f"(d[2]), "+f"(d[3])
        : "r"(a[0]), "r"(a[1]), "r"(a[2]), "r"(a[3]), "r"(b[0]), "r"(b[1]));
}
__device__ __forceinline__ uint32_t packh2(float a, float b) {
    __half2 h = __floats2half2_rn(a, b);
    return *(uint32_t*)&h;
}
__device__ __forceinline__ void split2(float a, float b, uint32_t& hi, uint32_t& lo) {
    __nv_bfloat162 h2 = __floats2bfloat162_rn(a, b);
    float ar = a - __bfloat162float(h2.x);
    float br = b - __bfloat162float(h2.y);
    __nv_bfloat162 l2 = __floats2bfloat162_rn(ar, br);
    hi = *(uint32_t*)&h2;
    lo = *(uint32_t*)&l2;
}
__device__ __forceinline__ void split2h(float a, float b, uint32_t& hi, uint32_t& lo) {
    __half2 h2 = __floats2half2_rn(a, b);
    float ar = a - __half2float(__low2half(h2));
    float br = b - __half2float(__high2half(h2));
    __half2 l2 = __floats2half2_rn(ar, br);
    hi = *(uint32_t*)&h2;
    lo = *(uint32_t*)&l2;
}

// ---------------------------------------------------------------------------
// Prep: split W into packed bf16 hi/lo pairs.
// ---------------------------------------------------------------------------
__global__ void prep_w(const float* __restrict__ Wq, const float* __restrict__ Wk,
                       const float* __restrict__ Wv)
{
    int idx = blockIdx.x * 256 + threadIdx.x;
    if (idx >= 192 * 512) return;
    int row = idx >> 9;
    int pc  = idx & 511;
    const float* src = (row < 64)  ? Wq + (size_t)row * ED
                     : (row < 128) ? Wk + (size_t)(row - 64) * ED
                                   : Wv + (size_t)(row - 128) * ED;
    uint32_t h, l;
    split2(src[pc * 2], src[pc * 2 + 1], h, l);
    g_whp[idx] = h;
    g_wlp[idx] = l;
}

// ---------------------------------------------------------------------------
// QKV via bf16 m16n8k16, 3-term split. (Unchanged from round 5 — measured
// at the legacy-HMMA tensor roofline.)
// ---------------------------------------------------------------------------
__global__ __launch_bounds__(256, 2)
void qkv_kernel(const float* __restrict__ x,
                const float* __restrict__ bq, const float* __restrict__ bk,
                const float* __restrict__ bv)
{
    __shared__ uint32_t xs_h[64][20],  xs_l[64][20];
    __shared__ uint32_t ws_h[192][20], ws_l[192][20];

    const int t    = threadIdx.x;
    const int lane = t & 31;
    const int wid  = t >> 5;
    const int wm   = wid & 1;
    const int wn   = wid >> 1;
    const int gq   = lane >> 2;
    const int tg   = lane & 3;
    const size_t rowBase = (size_t)blockIdx.x * 64;

    float acc[2][6][4];
    #pragma unroll
    for (int mi = 0; mi < 2; mi++)
        #pragma unroll
        for (int ni = 0; ni < 6; ni++)
            #pragma unroll
            for (int j = 0; j < 4; j++) acc[mi][ni][j] = 0.f;

    const int xr = t >> 2;
    const int xc = (t & 3) * 8;

    for (int ch = 0; ch < 32; ch++) {
        __syncthreads();
        {
            const float* xp = x + (rowBase + xr) * ED + ch * 32 + xc;
            float4 f0 = *(const float4*)xp;
            float4 f1 = *(const float4*)(xp + 4);
            uint4 hv, lv;
            split2(f0.x, f0.y, hv.x, lv.x);
            split2(f0.z, f0.w, hv.y, lv.y);
            split2(f1.x, f1.y, hv.z, lv.z);
            split2(f1.z, f1.w, hv.w, lv.w);
            *(uint4*)&xs_h[xr][(t & 3) * 4] = hv;
            *(uint4*)&xs_l[xr][(t & 3) * 4] = lv;
        }
        #pragma unroll
        for (int i = 0; i < 3; i++) {
            int slot = t + i * 256;
            int r = slot >> 2, c4 = (slot & 3) * 4;
            *(uint4*)&ws_h[r][c4] = *(const uint4*)&g_whp[r * 512 + ch * 16 + c4];
            *(uint4*)&ws_l[r][c4] = *(const uint4*)&g_wlp[r * 512 + ch * 16 + c4];
        }
        __syncthreads();

        #pragma unroll
        for (int kk = 0; kk < 2; kk++) {
            const int c0 = kk * 8 + tg;
            uint32_t ah[2][4], al[2][4];
            #pragma unroll
            for (int mi = 0; mi < 2; mi++) {
                int r0 = wm * 32 + mi * 16 + gq;
                ah[mi][0] = xs_h[r0][c0];     ah[mi][1] = xs_h[r0 + 8][c0];
                ah[mi][2] = xs_h[r0][c0 + 4]; ah[mi][3] = xs_h[r0 + 8][c0 + 4];
                al[mi][0] = xs_l[r0][c0];     al[mi][1] = xs_l[r0 + 8][c0];
                al[mi][2] = xs_l[r0][c0 + 4]; al[mi][3] = xs_l[r0 + 8][c0 + 4];
            }
            uint32_t bh[6][2], bl[6][2];
            #pragma unroll
            for (int ni = 0; ni < 6; ni++) {
                int n0 = wn * 48 + ni * 8 + gq;
                bh[ni][0] = ws_h[n0][c0]; bh[ni][1] = ws_h[n0][c0 + 4];
                bl[ni][0] = ws_l[n0][c0]; bl[ni][1] = ws_l[n0][c0 + 4];
            }
            #pragma unroll
            for (int mi = 0; mi < 2; mi++)
                #pragma unroll
                for (int ni = 0; ni < 6; ni++) mma_bf16(acc[mi][ni], ah[mi], bh[ni]);
            #pragma unroll
            for (int mi = 0; mi < 2; mi++)
                #pragma unroll
                for (int ni = 0; ni < 6; ni++) mma_bf16(acc[mi][ni], ah[mi], bl[ni]);
            #pragma unroll
            for (int mi = 0; mi < 2; mi++)
                #pragma unroll
                for (int ni = 0; ni < 6; ni++) mma_bf16(acc[mi][ni], al[mi], bh[ni]);
        }
    }

    #pragma unroll
    for (int ni = 0; ni < 6; ni++) {
        const int gc0 = wn * 48 + ni * 8;
        const int wi  = gc0 >> 6;
        const int h0  = (gc0 & 63) + tg * 2;
        float* outp      = (wi == 0) ? g_q : (wi == 1) ? g_k : g_v;
        const float* bp  = (wi == 0) ? bq  : (wi == 1) ? bk  : bv;
        const float b0 = bp[h0], b1 = bp[h0 + 1];
        #pragma unroll
        for (int mi = 0; mi < 2; mi++) {
            size_t r = rowBase + wm * 32 + mi * 16 + gq;
            *(float2*)(outp + r * HD + h0) =
                make_float2(acc[mi][ni][0] + b0, acc[mi][ni][1] + b1);
            *(float2*)(outp + (r + 8) * HD + h0) =
                make_float2(acc[mi][ni][2] + b0, acc[mi][ni][3] + b1);
        }
    }
}

// ---------------------------------------------------------------------------
// Causal flash attention. 512 threads = 4 k-split groups x 4 warps over one
// BQ=64 q-tile. Group g owns 32-row k-tiles 4j+g (group-local named
// barriers), 4-way analytic merge. exp2-folded scale, ballot-gated rescale.
// Grid (16 pairs, 8 b): q-tiles {p, 31-p} per CTA.
// ---------------------------------------------------------------------------
#define GROUP_BAR(gid) asm volatile("bar.sync %0, 128;" :: "r"((gid) + 1) : "memory")

__global__ __launch_bounds__(512, 1)
void attn_kernel(float* __restrict__ out)
{
    __shared__ __align__(16) uint32_t sbuf[9728];   // 4 x (kst[32][36] + vt[64][20])

    const int t    = threadIdx.x;
    const int lane = t & 31;
    const int wid  = t >> 5;       // 0..15
    const int g    = wid >> 2;     // k-split group 0..3
    const int qb   = wid & 3;      // q-block 0..3 (16 rows each)
    const int gq   = lane >> 2;
    const int tg   = lane & 3;
    const int tl   = t & 127;      // thread within group
    const int b    = blockIdx.y;
    const size_t bOff = (size_t)b * SEQ * HD;

    uint32_t* kst = sbuf + g * 2432;          // [32][36]
    uint32_t* vt  = sbuf + g * 2432 + 1152;   // [64][20]
    float* obuf = (float*)sbuf;               // merge overlay [64][68]
    float* mlb  = (float*)(sbuf + 4352);      // merge overlay m,l

    const int klr  = tl >> 2;          // K: row 0..31
    const int klc  = tl & 3;           // K: 16-float col block
    const int vlc  = tl >> 3;          // V: h quad 0..15
    const int vlr4 = (tl & 7) * 4;     // V: 4-row base

    const float SC2 = 0.18033688f;     // log2(e) / 8

    for (int pass = 0; pass < 2; pass++) {
        __syncthreads();               // overlay + all tiles safe before reuse
        const int qt = pass ? (31 - blockIdx.x) : blockIdx.x;
        const int qbase = qt * 64;
        const int r0l = qb * 16 + gq;

        // Q fragments (fp16 2-term split) with log2e/8 pre-folded
        uint32_t qh2[4][4], ql2[4][4];
        {
            const float* qp = g_q + bOff + (size_t)(qbase + r0l) * HD;
            #pragma unroll
            for (int c = 0; c < 4; c++) {
                int c0 = c * 16 + tg * 2;
                float2 f00 = *(const float2*)(qp + c0);
                float2 f10 = *(const float2*)(qp + 8 * HD + c0);
                float2 f01 = *(const float2*)(qp + c0 + 8);
                float2 f11 = *(const float2*)(qp + 8 * HD + c0 + 8);
                split2h(f00.x * SC2, f00.y * SC2, qh2[c][0], ql2[c][0]);
                split2h(f10.x * SC2, f10.y * SC2, qh2[c][1], ql2[c][1]);
                split2h(f01.x * SC2, f01.y * SC2, qh2[c][2], ql2[c][2]);
                split2h(f11.x * SC2, f11.y * SC2, qh2[c][3], ql2[c][3]);
            }
        }

        float m0 = -1e30f, m1 = -1e30f, l0 = 0.f, l1 = 0.f;
        float O[8][4];
        #pragma unroll
        for (int nh = 0; nh < 8; nh++)
            #pragma unroll
            for (int j = 0; j < 4; j++) O[nh][j] = 0.f;

        const int ng = (g <= 2 * qt + 1) ? (((2 * qt + 1 - g) >> 2) + 1) : 0;

        for (int j = 0; j < ng; j++) {
            const int kbase = (4 * j + g) * 32;
            GROUP_BAR(g);   // group done reading previous tile
            // K tile -> packed fp16 pairs [krow][hpair]
            {
                const float* kp = g_k + bOff + (size_t)(kbase + klr) * HD + klc * 16;
                uint32_t pr[8];
                #pragma unroll
                for (int q4 = 0; q4 < 4; q4++) {
                    float4 f = *(const float4*)(kp + q4 * 4);
                    pr[q4 * 2]     = packh2(f.x, f.y);
                    pr[q4 * 2 + 1] = packh2(f.z, f.w);
                }
                uint32_t* dst = kst + klr * 36 + klc * 8;
                *(uint4*)dst       = make_uint4(pr[0], pr[1], pr[2], pr[3]);
                *(uint4*)(dst + 4) = make_uint4(pr[4], pr[5], pr[6], pr[7]);
            }
            // V tile -> transposed packed pairs [h][krow-pair]
            {
                const float* vp = g_v + bOff + (size_t)(kbase + vlr4) * HD + vlc * 4;
                float4 v0 = *(const float4*)vp;
                float4 v1 = *(const float4*)(vp + HD);
                float4 v2 = *(const float4*)(vp + 2 * HD);
                float4 v3 = *(const float4*)(vp + 3 * HD);
                uint32_t* base = vt + (vlc * 4) * 20 + (vlr4 >> 1);
                *(uint2*)(base)      = make_uint2(packh2(v0.x, v1.x), packh2(v2.x, v3.x));
                *(uint2*)(base + 20) = make_uint2(packh2(v0.y, v1.y), packh2(v2.y, v3.y));
                *(uint2*)(base + 40) = make_uint2(packh2(v0.z, v1.z), packh2(v2.z, v3.z));
                *(uint2*)(base + 60) = make_uint2(packh2(v0.w, v1.w), packh2(v2.w, v3.w));
            }
            GROUP_BAR(g);   // tile visible

            // ---- S = Q K^T (pre-scaled by log2e/8) ----
            float s[4][4];
            #pragma unroll
            for (int nk = 0; nk < 4; nk++)
                #pragma unroll
                for (int j2 = 0; j2 < 4; j2++) s[nk][j2] = 0.f;

            #pragma unroll
            for (int c = 0; c < 4; c++) {
                uint32_t bfr[4][2];
                #pragma unroll
                for (int nk = 0; nk < 4; nk++) {
                    const uint32_t* kr = kst + (nk * 8 + gq) * 36 + c * 8 + tg;
                    bfr[nk][0] = kr[0];
                    bfr[nk][1] = kr[4];
                }
                #pragma unroll
                for (int nk = 0; nk < 4; nk++) mma_f16(s[nk], qh2[c], bfr[nk]);
                #pragma unroll
                for (int nk = 0; nk < 4; nk++) mma_f16(s[nk], ql2[c], bfr[nk]);
            }

            // ---- causal mask (diagonal-crossing tiles only; scale pre-folded) ----
            if (kbase + 31 > qbase) {
                const int row0 = qbase + r0l, row1 = row0 + 8;
                #pragma unroll
                for (int nk = 0; nk < 4; nk++) {
                    int c = kbase + nk * 8 + tg * 2;
                    if (c     > row0) s[nk][0] = -1e30f;
                    if (c + 1 > row0) s[nk][1] = -1e30f;
                    if (c     > row1) s[nk][2] = -1e30f;
                    if (c + 1 > row1) s[nk][3] = -1e30f;
                }
            }

            // ---- online softmax (base-2) ----
            float rm0 = -1e30f, rm1 = -1e30f;
            #pragma unroll
            for (int nk = 0; nk < 4; nk++) {
                rm0 = fmaxf(rm0, fmaxf(s[nk][0], s[nk][1]));
                rm1 = fmaxf(rm1, fmaxf(s[nk][2], s[nk][3]));
            }
            rm0 = fmaxf(rm0, __shfl_xor_sync(0xffffffffu, rm0, 1));
            rm0 = fmaxf(rm0, __shfl_xor_sync(0xffffffffu, rm0, 2));
            rm1 = fmaxf(rm1, __shfl_xor_sync(0xffffffffu, rm1, 1));
            rm1 = fmaxf(rm1, __shfl_xor_sync(0xffffffffu, rm1, 2));

            bool need = (rm0 > m0) | (rm1 > m1);
            if (__ballot_sync(0xffffffffu, need)) {
                float mn0 = fmaxf(m0, rm0), mn1 = fmaxf(m1, rm1);
                float a0 = exp2f(m0 - mn0), a1 = exp2f(m1 - mn1);
                m0 = mn0; m1 = mn1;
                l0 *= a0; l1 *= a1;
                #pragma unroll
                for (int nh = 0; nh < 8; nh++) {
                    O[nh][0] *= a0; O[nh][1] *= a0;
                    O[nh][2] *= a1; O[nh][3] *= a1;
                }
            }

            float rs0 = 0.f, rs1 = 0.f;
            #pragma unroll
            for (int nk = 0; nk < 4; nk++) {
                s[nk][0] = exp2f(s[nk][0] - m0); rs0 += s[nk][0];
                s[nk][1] = exp2f(s[nk][1] - m0); rs0 += s[nk][1];
                s[nk][2] = exp2f(s[nk][2] - m1); rs1 += s[nk][2];
                s[nk][3] = exp2f(s[nk][3] - m1); rs1 += s[nk][3];
            }
            rs0 += __shfl_xor_sync(0xffffffffu, rs0, 1);
            rs0 += __shfl_xor_sync(0xffffffffu, rs0, 2);
            rs1 += __shfl_xor_sync(0xffffffffu, rs1, 1);
            rs1 += __shfl_xor_sync(0xffffffffu, rs1, 2);
            l0 += rs0;
            l1 += rs1;

            // ---- O += P V ----
            #pragma unroll
            for (int c = 0; c < 2; c++) {
                uint32_t pa[4];
                pa[0] = packh2(s[2 * c][0],     s[2 * c][1]);
                pa[1] = packh2(s[2 * c][2],     s[2 * c][3]);
                pa[2] = packh2(s[2 * c + 1][0], s[2 * c + 1][1]);
                pa[3] = packh2(s[2 * c + 1][2], s[2 * c + 1][3]);
                #pragma unroll
                for (int nh = 0; nh < 8; nh++) {
                    const uint32_t* vr = vt + (nh * 8 + gq) * 20 + c * 8 + tg;
                    uint32_t vb[2];
                    vb[0] = vr[0];
                    vb[1] = vr[4];
                    mma_f16(O[nh], pa, vb);
                }
            }
        }

        // ---- 4-way merge: groups 1..3 feed group 0 ----
        __syncthreads();
        #pragma unroll
        for (int r = 1; r < 4; r++) {
            if (g == r) {
                mlb[r0l * 2]           = m0;
                mlb[r0l * 2 + 1]       = l0;
                mlb[(r0l + 8) * 2]     = m1;
                mlb[(r0l + 8) * 2 + 1] = l1;
                #pragma unroll
                for (int nh = 0; nh < 8; nh++) {
                    int c = nh * 8 + tg * 2;
                    *(float2*)&obuf[r0l * 68 + c]       = make_float2(O[nh][0], O[nh][1]);
                    *(float2*)&obuf[(r0l + 8) * 68 + c] = make_float2(O[nh][2], O[nh][3]);
                }
            }
            __syncthreads();
            if (g == 0) {
                float mb0 = mlb[r0l * 2],       lb0 = mlb[r0l * 2 + 1];
                float mb1 = mlb[(r0l + 8) * 2], lb1 = mlb[(r0l + 8) * 2 + 1];
                float M0 = fmaxf(m0, mb0), M1 = fmaxf(m1, mb1);
                float ea0 = exp2f(m0 - M0),  eb0 = exp2f(mb0 - M0);
                float ea1 = exp2f(m1 - M1),  eb1 = exp2f(mb1 - M1);
                l0 = l0 * ea0 + lb0 * eb0;
                l1 = l1 * ea1 + lb1 * eb1;
                m0 = M0; m1 = M1;
                #pragma unroll
                for (int nh = 0; nh < 8; nh++) {
                    int c = nh * 8 + tg * 2;
                    float2 ob0 = *(float2*)&obuf[r0l * 68 + c];
                    float2 ob1 = *(float2*)&obuf[(r0l + 8) * 68 + c];
                    O[nh][0] = O[nh][0] * ea0 + ob0.x * eb0;
                    O[nh][1] = O[nh][1] * ea0 + ob0.y * eb0;
                    O[nh][2] = O[nh][2] * ea1 + ob1.x * eb1;
                    O[nh][3] = O[nh][3] * ea1 + ob1.y * eb1;
                }
            }
            __syncthreads();
        }

        if (g == 0) {
            const float inv0 = 1.f / l0, inv1 = 1.f / l1;
            const int r = qbase + r0l;
            #pragma unroll
            for (int nh = 0; nh < 8; nh++) {
                int c = nh * 8 + tg * 2;
                *(float2*)(out + bOff + (size_t)r * HD + c) =
                    make_float2(O[nh][0] * inv0, O[nh][1] * inv0);
                *(float2*)(out + bOff + (size_t)(r + 8) * HD + c) =
                    make_float2(O[nh][2] * inv1, O[nh][3] * inv1);
            }
        }
    }
}

// ---------------------------------------------------------------------------
extern "C" void kernel_launch(void* const* d_in, const int* in_sizes, int n_in,
                              void* d_out, int out_size)
{
    const float* x  = (const float*)d_in[0];
    const float* Wq = (const float*)d_in[1];
    const float* bq = (const float*)d_in[2];
    const float* Wk = (const float*)d_in[3];
    const float* bk = (const float*)d_in[4];
    const float* Wv = (const float*)d_in[5];
    const float* bv = (const float*)d_in[6];
    float* out = (float*)d_out;

    prep_w<<<384, 256>>>(Wq, Wk, Wv);
    qkv_kernel<<<(NB * SEQ) / 64, 256>>>(x, bq, bk, bv);
    attn_kernel<<<dim3(16, NB), 512>>>(out);
}

// round 8
// speedup vs baseline: 1.0460x; 1.0117x over previous
#include <cuda_runtime.h>
#include <cuda_bf16.h>
#include <cuda_fp16.h>
#include <cstdint>

#define NB   8
#define SEQ  2048
#define ED   1024
#define HD   64

__device__ float g_q[NB * SEQ * HD];
__device__ float g_k[NB * SEQ * HD];
__device__ float g_v[NB * SEQ * HD];
__device__ uint32_t g_whp[192 * 512];
__device__ uint32_t g_wlp[192 * 512];

// ---------------- helpers ----------------
__device__ __forceinline__ void mma_bf16(float* d, const uint32_t* a, const uint32_t* b) {
    asm("mma.sync.aligned.m16n8k16.row.col.f32.bf16.bf16.f32 "
        "{%0,%1,%2,%3}, {%4,%5,%6,%7}, {%8,%9}, {%0,%1,%2,%3};"
        : "+f"(d[0]), "+f"(d[1]), "+f"(d[2]), "+f"(d[3])
        : "r"(a[0]), "r"(a[1]), "r"(a[2]), "r"(a[3]), "r"(b[0]), "r"(b[1]));
}
__device__ __forceinline__ void mma_f16(float* d, const uint32_t* a, const uint32_t* b) {
    asm("mma.sync.aligned.m16n8k16.row.col.f32.f16.f16.f32 "
        "{%0,%1,%2,%3}, {%4,%5,%6,%7}, {%8,%9}, {%0,%1,%2,%3};"
        : "+f"(d[0]), "+f"(d[1]), "+f"(d[2]), "+f"(d[3])
        : "r"(a[0]), "r"(a[1]), "r"(a[2]), "r"(a[3]), "r"(b[0]), "r"(b[1]));
}
__device__ __forceinline__ uint32_t packh2(float a, float b) {
    __half2 h = __floats2half2_rn(a, b);
    return *(uint32_t*)&h;
}
__device__ __forceinline__ void split2(float a, float b, uint32_t& hi, uint32_t& lo) {
    __nv_bfloat162 h2 = __floats2bfloat162_rn(a, b);
    float ar = a - __bfloat162float(h2.x);
    float br = b - __bfloat162float(h2.y);
    __nv_bfloat162 l2 = __floats2bfloat162_rn(ar, br);
    hi = *(uint32_t*)&h2;
    lo = *(uint32_t*)&l2;
}
__device__ __forceinline__ void split2h(float a, float b, uint32_t& hi, uint32_t& lo) {
    __half2 h2 = __floats2half2_rn(a, b);
    float ar = a - __half2float(__low2half(h2));
    float br = b - __half2float(__high2half(h2));
    __half2 l2 = __floats2half2_rn(ar, br);
    hi = *(uint32_t*)&h2;
    lo = *(uint32_t*)&l2;
}

// ---------------------------------------------------------------------------
// Prep: split W into packed bf16 hi/lo pairs (4 pairs per thread).
// ---------------------------------------------------------------------------
__global__ void prep_w(const float* __restrict__ Wq, const float* __restrict__ Wk,
                       const float* __restrict__ Wv)
{
    int idx4 = blockIdx.x * 256 + threadIdx.x;     // 24576 threads, 4 pairs each
    int row = idx4 >> 7;                           // 128 pair-quads per row
    int pq  = idx4 & 127;
    const float* src = (row < 64)  ? Wq + (size_t)row * ED
                     : (row < 128) ? Wk + (size_t)(row - 64) * ED
                                   : Wv + (size_t)(row - 128) * ED;
    float4 f0 = *(const float4*)(src + pq * 8);
    float4 f1 = *(const float4*)(src + pq * 8 + 4);
    uint4 h, l;
    split2(f0.x, f0.y, h.x, l.x);
    split2(f0.z, f0.w, h.y, l.y);
    split2(f1.x, f1.y, h.z, l.z);
    split2(f1.z, f1.w, h.w, l.w);
    *(uint4*)&g_whp[row * 512 + pq * 4] = h;
    *(uint4*)&g_wlp[row * 512 + pq * 4] = l;
}

// ---------------------------------------------------------------------------
// QKV via bf16 m16n8k16, 3-term split (unchanged — at legacy-HMMA roofline).
// ---------------------------------------------------------------------------
__global__ __launch_bounds__(256, 2)
void qkv_kernel(const float* __restrict__ x,
                const float* __restrict__ bq, const float* __restrict__ bk,
                const float* __restrict__ bv)
{
    __shared__ uint32_t xs_h[64][20],  xs_l[64][20];
    __shared__ uint32_t ws_h[192][20], ws_l[192][20];

    const int t    = threadIdx.x;
    const int lane = t & 31;
    const int wid  = t >> 5;
    const int wm   = wid & 1;
    const int wn   = wid >> 1;
    const int gq   = lane >> 2;
    const int tg   = lane & 3;
    const size_t rowBase = (size_t)blockIdx.x * 64;

    float acc[2][6][4];
    #pragma unroll
    for (int mi = 0; mi < 2; mi++)
        #pragma unroll
        for (int ni = 0; ni < 6; ni++)
            #pragma unroll
            for (int j = 0; j < 4; j++) acc[mi][ni][j] = 0.f;

    const int xr = t >> 2;
    const int xc = (t & 3) * 8;

    for (int ch = 0; ch < 32; ch++) {
        __syncthreads();
        {
            const float* xp = x + (rowBase + xr) * ED + ch * 32 + xc;
            float4 f0 = *(const float4*)xp;
            float4 f1 = *(const float4*)(xp + 4);
            uint4 hv, lv;
            split2(f0.x, f0.y, hv.x, lv.x);
            split2(f0.z, f0.w, hv.y, lv.y);
            split2(f1.x, f1.y, hv.z, lv.z);
            split2(f1.z, f1.w, hv.w, lv.w);
            *(uint4*)&xs_h[xr][(t & 3) * 4] = hv;
            *(uint4*)&xs_l[xr][(t & 3) * 4] = lv;
        }
        #pragma unroll
        for (int i = 0; i < 3; i++) {
            int slot = t + i * 256;
            int r = slot >> 2, c4 = (slot & 3) * 4;
            *(uint4*)&ws_h[r][c4] = *(const uint4*)&g_whp[r * 512 + ch * 16 + c4];
            *(uint4*)&ws_l[r][c4] = *(const uint4*)&g_wlp[r * 512 + ch * 16 + c4];
        }
        __syncthreads();

        #pragma unroll
        for (int kk = 0; kk < 2; kk++) {
            const int c0 = kk * 8 + tg;
            uint32_t ah[2][4], al[2][4];
            #pragma unroll
            for (int mi = 0; mi < 2; mi++) {
                int r0 = wm * 32 + mi * 16 + gq;
                ah[mi][0] = xs_h[r0][c0];     ah[mi][1] = xs_h[r0 + 8][c0];
                ah[mi][2] = xs_h[r0][c0 + 4]; ah[mi][3] = xs_h[r0 + 8][c0 + 4];
                al[mi][0] = xs_l[r0][c0];     al[mi][1] = xs_l[r0 + 8][c0];
                al[mi][2] = xs_l[r0][c0 + 4]; al[mi][3] = xs_l[r0 + 8][c0 + 4];
            }
            uint32_t bh[6][2], bl[6][2];
            #pragma unroll
            for (int ni = 0; ni < 6; ni++) {
                int n0 = wn * 48 + ni * 8 + gq;
                bh[ni][0] = ws_h[n0][c0]; bh[ni][1] = ws_h[n0][c0 + 4];
                bl[ni][0] = ws_l[n0][c0]; bl[ni][1] = ws_l[n0][c0 + 4];
            }
            #pragma unroll
            for (int mi = 0; mi < 2; mi++)
                #pragma unroll
                for (int ni = 0; ni < 6; ni++) mma_bf16(acc[mi][ni], ah[mi], bh[ni]);
            #pragma unroll
            for (int mi = 0; mi < 2; mi++)
                #pragma unroll
                for (int ni = 0; ni < 6; ni++) mma_bf16(acc[mi][ni], ah[mi], bl[ni]);
            #pragma unroll
            for (int mi = 0; mi < 2; mi++)
                #pragma unroll
                for (int ni = 0; ni < 6; ni++) mma_bf16(acc[mi][ni], al[mi], bh[ni]);
        }
    }

    #pragma unroll
    for (int ni = 0; ni < 6; ni++) {
        const int gc0 = wn * 48 + ni * 8;
        const int wi  = gc0 >> 6;
        const int h0  = (gc0 & 63) + tg * 2;
        float* outp      = (wi == 0) ? g_q : (wi == 1) ? g_k : g_v;
        const float* bp  = (wi == 0) ? bq  : (wi == 1) ? bk  : bv;
        const float b0 = bp[h0], b1 = bp[h0 + 1];
        #pragma unroll
        for (int mi = 0; mi < 2; mi++) {
            size_t r = rowBase + wm * 32 + mi * 16 + gq;
            *(float2*)(outp + r * HD + h0) =
                make_float2(acc[mi][ni][0] + b0, acc[mi][ni][1] + b1);
            *(float2*)(outp + (r + 8) * HD + h0) =
                make_float2(acc[mi][ni][2] + b0, acc[mi][ni][3] + b1);
        }
    }
}

// ---------------------------------------------------------------------------
// Causal flash attention v4. 512 threads = 4 k-split groups x 4 warps.
// BK=64 k-tiles, double-buffered packed-fp16 smem (dynamic 144KB), ONE group
// barrier per round: load(j+1) -> compute(j) -> bar. Grid (16,8): q-tiles
// {p, 31-p} per CTA. Group g owns k-tiles j%4==g; 4-way analytic merge.
// ---------------------------------------------------------------------------
#define GROUP_BAR(gid) asm volatile("bar.sync %0, 128;" :: "r"((gid) + 1) : "memory")
#define ATTN_SMEM (147456)

extern __shared__ uint32_t sbuf[];

__global__ __launch_bounds__(512, 1)
void attn_kernel(float* __restrict__ out)
{
    const int t    = threadIdx.x;
    const int lane = t & 31;
    const int wid  = t >> 5;       // 0..15
    const int g    = wid >> 2;     // k-split group 0..3
    const int qb   = wid & 3;      // q-block (16 rows)
    const int gq   = lane >> 2;
    const int tg   = lane & 3;
    const int tl   = t & 127;      // thread within group
    const int b    = blockIdx.y;
    const size_t bOff = (size_t)b * SEQ * HD;

    const uint32_t gbase = g * 9216;          // 2 buffers x 4608 u32
    float* obuf = (float*)sbuf;               // merge overlay [64][68]
    float* mlb  = (float*)(sbuf + 4352);

    // K loader: coalesced. chunk = 16B col block, rowbase + 16*i rows.
    const int kck = tl & 7;            // col chunk (floats kck*4..+3) then +32
    const int krb = tl >> 3;           // row base 0..15
    // V loader: vlc = h quad, vlr4 = 4-row base
    const int vlc  = tl >> 3;
    const int vlr4 = (tl & 7) * 4;

    const float SC2 = 0.18033688f;     // log2(e) / 8

    for (int pass = 0; pass < 2; pass++) {
        __syncthreads();               // overlay + buffers safe before reuse
        const int qt = pass ? (31 - blockIdx.x) : blockIdx.x;
        const int qbase = qt * 64;
        const int r0l = qb * 16 + gq;

        // Q fragments (fp16 2-term split) with log2e/8 pre-folded
        uint32_t qh2[4][4], ql2[4][4];
        {
            const float* qp = g_q + bOff + (size_t)(qbase + r0l) * HD;
            #pragma unroll
            for (int c = 0; c < 4; c++) {
                int c0 = c * 16 + tg * 2;
                float2 f00 = *(const float2*)(qp + c0);
                float2 f10 = *(const float2*)(qp + 8 * HD + c0);
                float2 f01 = *(const float2*)(qp + c0 + 8);
                float2 f11 = *(const float2*)(qp + 8 * HD + c0 + 8);
                split2h(f00.x * SC2, f00.y * SC2, qh2[c][0], ql2[c][0]);
                split2h(f10.x * SC2, f10.y * SC2, qh2[c][1], ql2[c][1]);
                split2h(f01.x * SC2, f01.y * SC2, qh2[c][2], ql2[c][2]);
                split2h(f11.x * SC2, f11.y * SC2, qh2[c][3], ql2[c][3]);
            }
        }

        float m0 = -1e30f, m1 = -1e30f, l0 = 0.f, l1 = 0.f;
        float O[8][4];
        #pragma unroll
        for (int nh = 0; nh < 8; nh++)
            #pragma unroll
            for (int j = 0; j < 4; j++) O[nh][j] = 0.f;

        const int ng = (qt >= g) ? (((qt - g) >> 2) + 1) : 0;

        // ---- tile loader (lambda-free macro-ish) ----
        #define LOAD_TILE(KB, BUFI) do {                                            \
            uint32_t* kst_ = sbuf + gbase + (BUFI) * 4608;                          \
            uint32_t* vt_  = kst_ + 2304;                                           \
            /* K: 8 coalesced LDG.128, cvt, STS.64 */                               \
            {                                                                       \
                float4 kf[8];                                                       \
                _Pragma("unroll")                                                   \
                for (int i = 0; i < 4; i++) {                                       \
                    const float* kp = g_k + bOff + (size_t)((KB) + krb + i * 16) * HD; \
                    kf[i * 2]     = *(const float4*)(kp + kck * 4);                 \
                    kf[i * 2 + 1] = *(const float4*)(kp + 32 + kck * 4);            \
                }                                                                   \
                _Pragma("unroll")                                                   \
                for (int i = 0; i < 4; i++) {                                       \
                    uint32_t* d0 = kst_ + (krb + i * 16) * 36 + kck * 2;            \
                    float4 a = kf[i * 2], c = kf[i * 2 + 1];                        \
                    *(uint2*)d0        = make_uint2(packh2(a.x, a.y), packh2(a.z, a.w)); \
                    *(uint2*)(d0 + 16) = make_uint2(packh2(c.x, c.y), packh2(c.z, c.w)); \
                }                                                                   \
            }                                                                       \
            /* V: transposed packed pairs [h][krow-pair] */                         \
            _Pragma("unroll")                                                       \
            for (int vb = 0; vb < 2; vb++) {                                        \
                int r0 = vlr4 + vb * 32;                                            \
                const float* vp = g_v + bOff + (size_t)((KB) + r0) * HD + vlc * 4;  \
                float4 v0 = *(const float4*)vp;                                     \
                float4 v1 = *(const float4*)(vp + HD);                              \
                float4 v2 = *(const float4*)(vp + 2 * HD);                          \
                float4 v3 = *(const float4*)(vp + 3 * HD);                          \
                uint32_t* base = vt_ + (vlc * 4) * 36 + (r0 >> 1);                  \
                *(uint2*)(base)       = make_uint2(packh2(v0.x, v1.x), packh2(v2.x, v3.x)); \
                *(uint2*)(base + 36)  = make_uint2(packh2(v0.y, v1.y), packh2(v2.y, v3.y)); \
                *(uint2*)(base + 72)  = make_uint2(packh2(v0.z, v1.z), packh2(v2.z, v3.z)); \
                *(uint2*)(base + 108) = make_uint2(packh2(v0.w, v1.w), packh2(v2.w, v3.w)); \
            }                                                                       \
        } while (0)

        if (ng > 0) {
            LOAD_TILE(g * 64, 0);
            GROUP_BAR(g);
        }

        for (int r = 0; r < ng; r++) {
            const int cur = r & 1;
            const int kbase = (4 * r + g) * 64;
            uint32_t* kst = sbuf + gbase + cur * 4608;
            uint32_t* vt  = kst + 2304;

            if (r + 1 < ng) LOAD_TILE((4 * (r + 1) + g) * 64, cur ^ 1);

            // ---- S = Q K^T (pre-scaled by log2e/8) ----
            float s[8][4];
            #pragma unroll
            for (int nk = 0; nk < 8; nk++)
                #pragma unroll
                for (int j2 = 0; j2 < 4; j2++) s[nk][j2] = 0.f;

            #pragma unroll
            for (int c = 0; c < 4; c++) {
                uint32_t bfr[8][2];
                #pragma unroll
                for (int nk = 0; nk < 8; nk++) {
                    const uint32_t* kr = kst + (nk * 8 + gq) * 36 + c * 8 + tg;
                    bfr[nk][0] = kr[0];
                    bfr[nk][1] = kr[4];
                }
                #pragma unroll
                for (int nk = 0; nk < 8; nk++) mma_f16(s[nk], qh2[c], bfr[nk]);
                #pragma unroll
                for (int nk = 0; nk < 8; nk++) mma_f16(s[nk], ql2[c], bfr[nk]);
            }

            // ---- causal mask: only the diagonal tile (kbase == qbase) ----
            if (kbase == qbase) {
                const int row0 = r0l, row1 = r0l + 8;   // local since kbase==qbase
                #pragma unroll
                for (int nk = 0; nk < 8; nk++) {
                    int c = nk * 8 + tg * 2;
                    if (c     > row0) s[nk][0] = -1e30f;
                    if (c + 1 > row0) s[nk][1] = -1e30f;
                    if (c     > row1) s[nk][2] = -1e30f;
                    if (c + 1 > row1) s[nk][3] = -1e30f;
                }
            }

            // ---- online softmax (base-2, always-rescale) ----
            float rm0 = -1e30f, rm1 = -1e30f;
            #pragma unroll
            for (int nk = 0; nk < 8; nk++) {
                rm0 = fmaxf(rm0, fmaxf(s[nk][0], s[nk][1]));
                rm1 = fmaxf(rm1, fmaxf(s[nk][2], s[nk][3]));
            }
            rm0 = fmaxf(rm0, __shfl_xor_sync(0xffffffffu, rm0, 1));
            rm0 = fmaxf(rm0, __shfl_xor_sync(0xffffffffu, rm0, 2));
            rm1 = fmaxf(rm1, __shfl_xor_sync(0xffffffffu, rm1, 1));
            rm1 = fmaxf(rm1, __shfl_xor_sync(0xffffffffu, rm1, 2));

            float mn0 = fmaxf(m0, rm0), mn1 = fmaxf(m1, rm1);
            float a0 = exp2f(m0 - mn0), a1 = exp2f(m1 - mn1);
            m0 = mn0; m1 = mn1;
            l0 *= a0; l1 *= a1;
            #pragma unroll
            for (int nh = 0; nh < 8; nh++) {
                O[nh][0] *= a0; O[nh][1] *= a0;
                O[nh][2] *= a1; O[nh][3] *= a1;
            }

            float rs0 = 0.f, rs1 = 0.f;
            #pragma unroll
            for (int nk = 0; nk < 8; nk++) {
                s[nk][0] = exp2f(s[nk][0] - m0); rs0 += s[nk][0];
                s[nk][1] = exp2f(s[nk][1] - m0); rs0 += s[nk][1];
                s[nk][2] = exp2f(s[nk][2] - m1); rs1 += s[nk][2];
                s[nk][3] = exp2f(s[nk][3] - m1); rs1 += s[nk][3];
            }
            rs0 += __shfl_xor_sync(0xffffffffu, rs0, 1);
            rs0 += __shfl_xor_sync(0xffffffffu, rs0, 2);
            rs1 += __shfl_xor_sync(0xffffffffu, rs1, 1);
            rs1 += __shfl_xor_sync(0xffffffffu, rs1, 2);
            l0 += rs0;
            l1 += rs1;

            // ---- O += P V ----
            #pragma unroll
            for (int c = 0; c < 4; c++) {
                uint32_t pa[4];
                pa[0] = packh2(s[2 * c][0],     s[2 * c][1]);
                pa[1] = packh2(s[2 * c][2],     s[2 * c][3]);
                pa[2] = packh2(s[2 * c + 1][0], s[2 * c + 1][1]);
                pa[3] = packh2(s[2 * c + 1][2], s[2 * c + 1][3]);
                #pragma unroll
                for (int nh = 0; nh < 8; nh++) {
                    const uint32_t* vr = vt + (nh * 8 + gq) * 36 + c * 8 + tg;
                    uint32_t vb[2];
                    vb[0] = vr[0];
                    vb[1] = vr[4];
                    mma_f16(O[nh], pa, vb);
                }
            }

            GROUP_BAR(g);   // STS(j+1) visible; buf[cur] free for round r+2
        }

        // ---- 4-way merge: groups 1..3 feed group 0 ----
        __syncthreads();
        #pragma unroll
        for (int rr = 1; rr < 4; rr++) {
            if (g == rr) {
                mlb[r0l * 2]           = m0;
                mlb[r0l * 2 + 1]       = l0;
                mlb[(r0l + 8) * 2]     = m1;
                mlb[(r0l + 8) * 2 + 1] = l1;
                #pragma unroll
                for (int nh = 0; nh < 8; nh++) {
                    int c = nh * 8 + tg * 2;
                    *(float2*)&obuf[r0l * 68 + c]       = make_float2(O[nh][0], O[nh][1]);
                    *(float2*)&obuf[(r0l + 8) * 68 + c] = make_float2(O[nh][2], O[nh][3]);
                }
            }
            __syncthreads();
            if (g == 0) {
                float mb0 = mlb[r0l * 2],       lb0 = mlb[r0l * 2 + 1];
                float mb1 = mlb[(r0l + 8) * 2], lb1 = mlb[(r0l + 8) * 2 + 1];
                float M0 = fmaxf(m0, mb0), M1 = fmaxf(m1, mb1);
                float ea0 = exp2f(m0 - M0),  eb0 = exp2f(mb0 - M0);
                float ea1 = exp2f(m1 - M1),  eb1 = exp2f(mb1 - M1);
                l0 = l0 * ea0 + lb0 * eb0;
                l1 = l1 * ea1 + lb1 * eb1;
                m0 = M0; m1 = M1;
                #pragma unroll
                for (int nh = 0; nh < 8; nh++) {
                    int c = nh * 8 + tg * 2;
                    float2 ob0 = *(float2*)&obuf[r0l * 68 + c];
                    float2 ob1 = *(float2*)&obuf[(r0l + 8) * 68 + c];
                    O[nh][0] = O[nh][0] * ea0 + ob0.x * eb0;
                    O[nh][1] = O[nh][1] * ea0 + ob0.y * eb0;
                    O[nh][2] = O[nh][2] * ea1 + ob1.x * eb1;
                    O[nh][3] = O[nh][3] * ea1 + ob1.y * eb1;
                }
            }
            __syncthreads();
        }

        if (g == 0) {
            const float inv0 = 1.f / l0, inv1 = 1.f / l1;
            const int r = qbase + r0l;
            #pragma unroll
            for (int nh = 0; nh < 8; nh++) {
                int c = nh * 8 + tg * 2;
                *(float2*)(out + bOff + (size_t)r * HD + c) =
                    make_float2(O[nh][0] * inv0, O[nh][1] * inv0);
                *(float2*)(out + bOff + (size_t)(r + 8) * HD + c) =
                    make_float2(O[nh][2] * inv1, O[nh][3] * inv1);
            }
        }
        #undef LOAD_TILE
    }
}

// ---------------------------------------------------------------------------
extern "C" void kernel_launch(void* const* d_in, const int* in_sizes, int n_in,
                              void* d_out, int out_size)
{
    const float* x  = (const float*)d_in[0];
    const float* Wq = (const float*)d_in[1];
    const float* bq = (const float*)d_in[2];
    const float* Wk = (const float*)d_in[3];
    const float* bk = (const float*)d_in[4];
    const float* Wv = (const float*)d_in[5];
    const float* bv = (const float*)d_in[6];
    float* out = (float*)d_out;

    cudaFuncSetAttribute(attn_kernel, cudaFuncAttributeMaxDynamicSharedMemorySize, ATTN_SMEM);

    prep_w<<<96, 256>>>(Wq, Wk, Wv);
    qkv_kernel<<<(NB * SEQ) / 64, 256>>>(x, bq, bk, bv);
    attn_kernel<<<dim3(16, NB), 512, ATTN_SMEM>>>(out);
}

// round 9
// speedup vs baseline: 1.0658x; 1.0189x over previous
#include <cuda_runtime.h>
#include <cuda_bf16.h>
#include <cuda_fp16.h>
#include <cstdint>

#define NB   8
#define SEQ  2048
#define ED   1024
#define HD   64

__device__ float g_q[NB * SEQ * HD];
__device__ float g_k[NB * SEQ * HD];
__device__ float g_v[NB * SEQ * HD];
__device__ uint32_t g_whp[192 * 512];
__device__ uint32_t g_wlp[192 * 512];

// ---------------- helpers ----------------
__device__ __forceinline__ void mma_bf16(float* d, const uint32_t* a, const uint32_t* b) {
    asm("mma.sync.aligned.m16n8k16.row.col.f32.bf16.bf16.f32 "
        "{%0,%1,%2,%3}, {%4,%5,%6,%7}, {%8,%9}, {%0,%1,%2,%3};"
        : "+f"(d[0]), "+f"(d[1]), "+f"(d[2]), "+f"(d[3])
        : "r"(a[0]), "r"(a[1]), "r"(a[2]), "r"(a[3]), "r"(b[0]), "r"(b[1]));
}
__device__ __forceinline__ void mma_f16(float* d, const uint32_t* a, const uint32_t* b) {
    asm("mma.sync.aligned.m16n8k16.row.col.f32.f16.f16.f32 "
        "{%0,%1,%2,%3}, {%4,%5,%6,%7}, {%8,%9}, {%0,%1,%2,%3};"
        : "+f"(d[0]), "+f"(d[1]), "+f"(d[2]), "+f"(d[3])
        : "r"(a[0]), "r"(a[1]), "r"(a[2]), "r"(a[3]), "r"(b[0]), "r"(b[1]));
}
__device__ __forceinline__ uint32_t packh2(float a, float b) {
    __half2 h = __floats2half2_rn(a, b);
    return *(uint32_t*)&h;
}
// packed half2 exp2 — ONE MUFU op for two exponentials
__device__ __forceinline__ uint32_t ex2h2(uint32_t in) {
    uint32_t r;
    asm("ex2.approx.f16x2 %0, %1;" : "=r"(r) : "r"(in));
    return r;
}
__device__ __forceinline__ void split2(float a, float b, uint32_t& hi, uint32_t& lo) {
    __nv_bfloat162 h2 = __floats2bfloat162_rn(a, b);
    float ar = a - __bfloat162float(h2.x);
    float br = b - __bfloat162float(h2.y);
    __nv_bfloat162 l2 = __floats2bfloat162_rn(ar, br);
    hi = *(uint32_t*)&h2;
    lo = *(uint32_t*)&l2;
}
__device__ __forceinline__ void split2h(float a, float b, uint32_t& hi, uint32_t& lo) {
    __half2 h2 = __floats2half2_rn(a, b);
    float ar = a - __half2float(__low2half(h2));
    float br = b - __half2float(__high2half(h2));
    __half2 l2 = __floats2half2_rn(ar, br);
    hi = *(uint32_t*)&h2;
    lo = *(uint32_t*)&l2;
}

// ---------------------------------------------------------------------------
// Prep: split W into packed bf16 hi/lo pairs.
// ---------------------------------------------------------------------------
__global__ void prep_w(const float* __restrict__ Wq, const float* __restrict__ Wk,
                       const float* __restrict__ Wv)
{
    int idx4 = blockIdx.x * 256 + threadIdx.x;
    int row = idx4 >> 7;
    int pq  = idx4 & 127;
    const float* src = (row < 64)  ? Wq + (size_t)row * ED
                     : (row < 128) ? Wk + (size_t)(row - 64) * ED
                                   : Wv + (size_t)(row - 128) * ED;
    float4 f0 = *(const float4*)(src + pq * 8);
    float4 f1 = *(const float4*)(src + pq * 8 + 4);
    uint4 h, l;
    split2(f0.x, f0.y, h.x, l.x);
    split2(f0.z, f0.w, h.y, l.y);
    split2(f1.x, f1.y, h.z, l.z);
    split2(f1.z, f1.w, h.w, l.w);
    *(uint4*)&g_whp[row * 512 + pq * 4] = h;
    *(uint4*)&g_wlp[row * 512 + pq * 4] = l;
}

// ---------------------------------------------------------------------------
// QKV via bf16 m16n8k16, 3-term split (unchanged — at legacy-HMMA roofline).
// ---------------------------------------------------------------------------
__global__ __launch_bounds__(256, 2)
void qkv_kernel(const float* __restrict__ x,
                const float* __restrict__ bq, const float* __restrict__ bk,
                const float* __restrict__ bv)
{
    __shared__ uint32_t xs_h[64][20],  xs_l[64][20];
    __shared__ uint32_t ws_h[192][20], ws_l[192][20];

    const int t    = threadIdx.x;
    const int lane = t & 31;
    const int wid  = t >> 5;
    const int wm   = wid & 1;
    const int wn   = wid >> 1;
    const int gq   = lane >> 2;
    const int tg   = lane & 3;
    const size_t rowBase = (size_t)blockIdx.x * 64;

    float acc[2][6][4];
    #pragma unroll
    for (int mi = 0; mi < 2; mi++)
        #pragma unroll
        for (int ni = 0; ni < 6; ni++)
            #pragma unroll
            for (int j = 0; j < 4; j++) acc[mi][ni][j] = 0.f;

    const int xr = t >> 2;
    const int xc = (t & 3) * 8;

    for (int ch = 0; ch < 32; ch++) {
        __syncthreads();
        {
            const float* xp = x + (rowBase + xr) * ED + ch * 32 + xc;
            float4 f0 = *(const float4*)xp;
            float4 f1 = *(const float4*)(xp + 4);
            uint4 hv, lv;
            split2(f0.x, f0.y, hv.x, lv.x);
            split2(f0.z, f0.w, hv.y, lv.y);
            split2(f1.x, f1.y, hv.z, lv.z);
            split2(f1.z, f1.w, hv.w, lv.w);
            *(uint4*)&xs_h[xr][(t & 3) * 4] = hv;
            *(uint4*)&xs_l[xr][(t & 3) * 4] = lv;
        }
        #pragma unroll
        for (int i = 0; i < 3; i++) {
            int slot = t + i * 256;
            int r = slot >> 2, c4 = (slot & 3) * 4;
            *(uint4*)&ws_h[r][c4] = *(const uint4*)&g_whp[r * 512 + ch * 16 + c4];
            *(uint4*)&ws_l[r][c4] = *(const uint4*)&g_wlp[r * 512 + ch * 16 + c4];
        }
        __syncthreads();

        #pragma unroll
        for (int kk = 0; kk < 2; kk++) {
            const int c0 = kk * 8 + tg;
            uint32_t ah[2][4], al[2][4];
            #pragma unroll
            for (int mi = 0; mi < 2; mi++) {
                int r0 = wm * 32 + mi * 16 + gq;
                ah[mi][0] = xs_h[r0][c0];     ah[mi][1] = xs_h[r0 + 8][c0];
                ah[mi][2] = xs_h[r0][c0 + 4]; ah[mi][3] = xs_h[r0 + 8][c0 + 4];
                al[mi][0] = xs_l[r0][c0];     al[mi][1] = xs_l[r0 + 8][c0];
                al[mi][2] = xs_l[r0][c0 + 4]; al[mi][3] = xs_l[r0 + 8][c0 + 4];
            }
            uint32_t bh[6][2], bl[6][2];
            #pragma unroll
            for (int ni = 0; ni < 6; ni++) {
                int n0 = wn * 48 + ni * 8 + gq;
                bh[ni][0] = ws_h[n0][c0]; bh[ni][1] = ws_h[n0][c0 + 4];
                bl[ni][0] = ws_l[n0][c0]; bl[ni][1] = ws_l[n0][c0 + 4];
            }
            #pragma unroll
            for (int mi = 0; mi < 2; mi++)
                #pragma unroll
                for (int ni = 0; ni < 6; ni++) mma_bf16(acc[mi][ni], ah[mi], bh[ni]);
            #pragma unroll
            for (int mi = 0; mi < 2; mi++)
                #pragma unroll
                for (int ni = 0; ni < 6; ni++) mma_bf16(acc[mi][ni], ah[mi], bl[ni]);
            #pragma unroll
            for (int mi = 0; mi < 2; mi++)
                #pragma unroll
                for (int ni = 0; ni < 6; ni++) mma_bf16(acc[mi][ni], al[mi], bh[ni]);
        }
    }

    #pragma unroll
    for (int ni = 0; ni < 6; ni++) {
        const int gc0 = wn * 48 + ni * 8;
        const int wi  = gc0 >> 6;
        const int h0  = (gc0 & 63) + tg * 2;
        float* outp      = (wi == 0) ? g_q : (wi == 1) ? g_k : g_v;
        const float* bp  = (wi == 0) ? bq  : (wi == 1) ? bk  : bv;
        const float b0 = bp[h0], b1 = bp[h0 + 1];
        #pragma unroll
        for (int mi = 0; mi < 2; mi++) {
            size_t r = rowBase + wm * 32 + mi * 16 + gq;
            *(float2*)(outp + r * HD + h0) =
                make_float2(acc[mi][ni][0] + b0, acc[mi][ni][1] + b1);
            *(float2*)(outp + (r + 8) * HD + h0) =
                make_float2(acc[mi][ni][2] + b0, acc[mi][ni][3] + b1);
        }
    }
}

// ---------------------------------------------------------------------------
// Causal flash attention v5. 512 threads = 4 k-split groups x 4 warps,
// BK=64 double-buffered tiles. Softmax: packed ex2.approx.f16x2 (P emitted
// directly as fp16 fragments, HALF the MUFU ops) + row-sum l via ones-MMA
// (tensor core computes sum-P; no shfl reductions).
// ---------------------------------------------------------------------------
#define GROUP_BAR(gid) asm volatile("bar.sync %0, 128;" :: "r"((gid) + 1) : "memory")
#define ATTN_SMEM (147456)

extern __shared__ uint32_t sbuf[];

__global__ __launch_bounds__(512, 1)
void attn_kernel(float* __restrict__ out)
{
    const int t    = threadIdx.x;
    const int lane = t & 31;
    const int wid  = t >> 5;
    const int g    = wid >> 2;
    const int qb   = wid & 3;
    const int gq   = lane >> 2;
    const int tg   = lane & 3;
    const int tl   = t & 127;
    const int b    = blockIdx.y;
    const size_t bOff = (size_t)b * SEQ * HD;

    const uint32_t gbase = g * 9216;
    float* obuf = (float*)sbuf;               // merge overlay [64][68]
    float* mlb  = (float*)(sbuf + 4352);

    const int kck = tl & 7;
    const int krb = tl >> 3;
    const int vlc  = tl >> 3;
    const int vlr4 = (tl & 7) * 4;

    const float SC2 = 0.18033688f;     // log2(e) / 8

    for (int pass = 0; pass < 2; pass++) {
        __syncthreads();
        const int qt = pass ? (31 - blockIdx.x) : blockIdx.x;
        const int qbase = qt * 64;
        const int r0l = qb * 16 + gq;

        uint32_t qh2[4][4], ql2[4][4];
        {
            const float* qp = g_q + bOff + (size_t)(qbase + r0l) * HD;
            #pragma unroll
            for (int c = 0; c < 4; c++) {
                int c0 = c * 16 + tg * 2;
                float2 f00 = *(const float2*)(qp + c0);
                float2 f10 = *(const float2*)(qp + 8 * HD + c0);
                float2 f01 = *(const float2*)(qp + c0 + 8);
                float2 f11 = *(const float2*)(qp + 8 * HD + c0 + 8);
                split2h(f00.x * SC2, f00.y * SC2, qh2[c][0], ql2[c][0]);
                split2h(f10.x * SC2, f10.y * SC2, qh2[c][1], ql2[c][1]);
                split2h(f01.x * SC2, f01.y * SC2, qh2[c][2], ql2[c][2]);
                split2h(f11.x * SC2, f11.y * SC2, qh2[c][3], ql2[c][3]);
            }
        }

        float m0 = -1e30f, m1 = -1e30f;
        float lacc[4] = {0.f, 0.f, 0.f, 0.f};
        float O[8][4];
        #pragma unroll
        for (int nh = 0; nh < 8; nh++)
            #pragma unroll
            for (int j = 0; j < 4; j++) O[nh][j] = 0.f;

        const int ng = (qt >= g) ? (((qt - g) >> 2) + 1) : 0;

        #define LOAD_TILE(KB, BUFI) do {                                            \
            uint32_t* kst_ = sbuf + gbase + (BUFI) * 4608;                          \
            uint32_t* vt_  = kst_ + 2304;                                           \
            {                                                                       \
                float4 kf[8];                                                       \
                _Pragma("unroll")                                                   \
                for (int i = 0; i < 4; i++) {                                       \
                    const float* kp = g_k + bOff + (size_t)((KB) + krb + i * 16) * HD; \
                    kf[i * 2]     = *(const float4*)(kp + kck * 4);                 \
                    kf[i * 2 + 1] = *(const float4*)(kp + 32 + kck * 4);            \
                }                                                                   \
                _Pragma("unroll")                                                   \
                for (int i = 0; i < 4; i++) {                                       \
                    uint32_t* d0 = kst_ + (krb + i * 16) * 36 + kck * 2;            \
                    float4 a = kf[i * 2], c = kf[i * 2 + 1];                        \
                    *(uint2*)d0        = make_uint2(packh2(a.x, a.y), packh2(a.z, a.w)); \
                    *(uint2*)(d0 + 16) = make_uint2(packh2(c.x, c.y), packh2(c.z, c.w)); \
                }                                                                   \
            }                                                                       \
            _Pragma("unroll")                                                       \
            for (int vb = 0; vb < 2; vb++) {                                        \
                int r0 = vlr4 + vb * 32;                                            \
                const float* vp = g_v + bOff + (size_t)((KB) + r0) * HD + vlc * 4;  \
                float4 v0 = *(const float4*)vp;                                     \
                float4 v1 = *(const float4*)(vp + HD);                              \
                float4 v2 = *(const float4*)(vp + 2 * HD);                          \
                float4 v3 = *(const float4*)(vp + 3 * HD);                          \
                uint32_t* base = vt_ + (vlc * 4) * 36 + (r0 >> 1);                  \
                *(uint2*)(base)       = make_uint2(packh2(v0.x, v1.x), packh2(v2.x, v3.x)); \
                *(uint2*)(base + 36)  = make_uint2(packh2(v0.y, v1.y), packh2(v2.y, v3.y)); \
                *(uint2*)(base + 72)  = make_uint2(packh2(v0.z, v1.z), packh2(v2.z, v3.z)); \
                *(uint2*)(base + 108) = make_uint2(packh2(v0.w, v1.w), packh2(v2.w, v3.w)); \
            }                                                                       \
        } while (0)

        if (ng > 0) {
            LOAD_TILE(g * 64, 0);
            GROUP_BAR(g);
        }

        for (int r = 0; r < ng; r++) {
            const int cur = r & 1;
            const int kbase = (4 * r + g) * 64;
            uint32_t* kst = sbuf + gbase + cur * 4608;
            uint32_t* vt  = kst + 2304;

            if (r + 1 < ng) LOAD_TILE((4 * (r + 1) + g) * 64, cur ^ 1);

            // ---- S = Q K^T (pre-scaled by log2e/8) ----
            float s[8][4];
            #pragma unroll
            for (int nk = 0; nk < 8; nk++)
                #pragma unroll
                for (int j2 = 0; j2 < 4; j2++) s[nk][j2] = 0.f;

            #pragma unroll
            for (int c = 0; c < 4; c++) {
                uint32_t bfr[8][2];
                #pragma unroll
                for (int nk = 0; nk < 8; nk++) {
                    const uint32_t* kr = kst + (nk * 8 + gq) * 36 + c * 8 + tg;
                    bfr[nk][0] = kr[0];
                    bfr[nk][1] = kr[4];
                }
                #pragma unroll
                for (int nk = 0; nk < 8; nk++) mma_f16(s[nk], qh2[c], bfr[nk]);
                #pragma unroll
                for (int nk = 0; nk < 8; nk++) mma_f16(s[nk], ql2[c], bfr[nk]);
            }

            // ---- causal mask: only the diagonal tile ----
            if (kbase == qbase) {
                const int row0 = r0l, row1 = r0l + 8;
                #pragma unroll
                for (int nk = 0; nk < 8; nk++) {
                    int c = nk * 8 + tg * 2;
                    if (c     > row0) s[nk][0] = -1e30f;
                    if (c + 1 > row0) s[nk][1] = -1e30f;
                    if (c     > row1) s[nk][2] = -1e30f;
                    if (c + 1 > row1) s[nk][3] = -1e30f;
                }
            }

            // ---- online max (base-2 domain) ----
            float rm0 = -1e30f, rm1 = -1e30f;
            #pragma unroll
            for (int nk = 0; nk < 8; nk++) {
                rm0 = fmaxf(rm0, fmaxf(s[nk][0], s[nk][1]));
                rm1 = fmaxf(rm1, fmaxf(s[nk][2], s[nk][3]));
            }
            rm0 = fmaxf(rm0, __shfl_xor_sync(0xffffffffu, rm0, 1));
            rm0 = fmaxf(rm0, __shfl_xor_sync(0xffffffffu, rm0, 2));
            rm1 = fmaxf(rm1, __shfl_xor_sync(0xffffffffu, rm1, 1));
            rm1 = fmaxf(rm1, __shfl_xor_sync(0xffffffffu, rm1, 2));

            float mn0 = fmaxf(m0, rm0), mn1 = fmaxf(m1, rm1);
            float a0 = exp2f(m0 - mn0), a1 = exp2f(m1 - mn1);
            m0 = mn0; m1 = mn1;
            lacc[0] *= a0; lacc[1] *= a0; lacc[2] *= a1; lacc[3] *= a1;
            #pragma unroll
            for (int nh = 0; nh < 8; nh++) {
                O[nh][0] *= a0; O[nh][1] *= a0;
                O[nh][2] *= a1; O[nh][3] *= a1;
            }

            // ---- P = exp2(s - m) via packed f16x2 MUFU; O += P V; l += P*1 ----
            const uint32_t ones2[2] = {0x3C003C00u, 0x3C003C00u};
            #pragma unroll
            for (int c = 0; c < 4; c++) {
                uint32_t pa[4];
                pa[0] = ex2h2(packh2(s[2 * c][0]     - m0, s[2 * c][1]     - m0));
                pa[1] = ex2h2(packh2(s[2 * c][2]     - m1, s[2 * c][3]     - m1));
                pa[2] = ex2h2(packh2(s[2 * c + 1][0] - m0, s[2 * c + 1][1] - m0));
                pa[3] = ex2h2(packh2(s[2 * c + 1][2] - m1, s[2 * c + 1][3] - m1));
                #pragma unroll
                for (int nh = 0; nh < 8; nh++) {
                    const uint32_t* vr = vt + (nh * 8 + gq) * 36 + c * 8 + tg;
                    uint32_t vb[2];
                    vb[0] = vr[0];
                    vb[1] = vr[4];
                    mma_f16(O[nh], pa, vb);
                }
                mma_f16(lacc, pa, ones2);
            }

            GROUP_BAR(g);
        }

        float l0 = lacc[0], l1 = lacc[2];

        // ---- 4-way merge: groups 1..3 feed group 0 ----
        __syncthreads();
        #pragma unroll
        for (int rr = 1; rr < 4; rr++) {
            if (g == rr) {
                mlb[r0l * 2]           = m0;
                mlb[r0l * 2 + 1]       = l0;
                mlb[(r0l + 8) * 2]     = m1;
                mlb[(r0l + 8) * 2 + 1] = l1;
                #pragma unroll
                for (int nh = 0; nh < 8; nh++) {
                    int c = nh * 8 + tg * 2;
                    *(float2*)&obuf[r0l * 68 + c]       = make_float2(O[nh][0], O[nh][1]);
                    *(float2*)&obuf[(r0l + 8) * 68 + c] = make_float2(O[nh][2], O[nh][3]);
                }
            }
            __syncthreads();
            if (g == 0) {
                float mb0 = mlb[r0l * 2],       lb0 = mlb[r0l * 2 + 1];
                float mb1 = mlb[(r0l + 8) * 2], lb1 = mlb[(r0l + 8) * 2 + 1];
                float M0 = fmaxf(m0, mb0), M1 = fmaxf(m1, mb1);
                float ea0 = exp2f(m0 - M0),  eb0 = exp2f(mb0 - M0);
                float ea1 = exp2f(m1 - M1),  eb1 = exp2f(mb1 - M1);
                l0 = l0 * ea0 + lb0 * eb0;
                l1 = l1 * ea1 + lb1 * eb1;
                m0 = M0; m1 = M1;
                #pragma unroll
                for (int nh = 0; nh < 8; nh++) {
                    int c = nh * 8 + tg * 2;
                    float2 ob0 = *(float2*)&obuf[r0l * 68 + c];
                    float2 ob1 = *(float2*)&obuf[(r0l + 8) * 68 + c];
                    O[nh][0] = O[nh][0] * ea0 + ob0.x * eb0;
                    O[nh][1] = O[nh][1] * ea0 + ob0.y * eb0;
                    O[nh][2] = O[nh][2] * ea1 + ob1.x * eb1;
                    O[nh][3] = O[nh][3] * ea1 + ob1.y * eb1;
                }
            }
            __syncthreads();
        }

        if (g == 0) {
            const float inv0 = 1.f / l0, inv1 = 1.f / l1;
            const int r = qbase + r0l;
            #pragma unroll
            for (int nh = 0; nh < 8; nh++) {
                int c = nh * 8 + tg * 2;
                *(float2*)(out + bOff + (size_t)r * HD + c) =
                    make_float2(O[nh][0] * inv0, O[nh][1] * inv0);
                *(float2*)(out + bOff + (size_t)(r + 8) * HD + c) =
                    make_float2(O[nh][2] * inv1, O[nh][3] * inv1);
            }
        }
        #undef LOAD_TILE
    }
}

// ---------------------------------------------------------------------------
extern "C" void kernel_launch(void* const* d_in, const int* in_sizes, int n_in,
                              void* d_out, int out_size)
{
    const float* x  = (const float*)d_in[0];
    const float* Wq = (const float*)d_in[1];
    const float* bq = (const float*)d_in[2];
    const float* Wk = (const float*)d_in[3];
    const float* bk = (const float*)d_in[4];
    const float* Wv = (const float*)d_in[5];
    const float* bv = (const float*)d_in[6];
    float* out = (float*)d_out;

    cudaFuncSetAttribute(attn_kernel, cudaFuncAttributeMaxDynamicSharedMemorySize, ATTN_SMEM);

    prep_w<<<96, 256>>>(Wq, Wk, Wv);
    qkv_kernel<<<(NB * SEQ) / 64, 256>>>(x, bq, bk, bv);
    attn_kernel<<<dim3(16, NB), 512, ATTN_SMEM>>>(out);
}

// round 10
// speedup vs baseline: 1.3957x; 1.3096x over previous
#include <cuda_runtime.h>
#include <cuda_bf16.h>
#include <cuda_fp16.h>
#include <cstdint>

#define NB   8
#define SEQ  2048
#define ED   1024
#define HD   64

__device__ float    g_q[NB * SEQ * HD];
__device__ uint32_t g_k16[NB * SEQ * 32];   // fp16x2-packed K (32 u32 per row)
__device__ uint32_t g_v16[NB * SEQ * 32];   // fp16x2-packed V

// ---------------- helpers ----------------
__device__ __forceinline__ void mma_bf16(float* d, const uint32_t* a, const uint32_t* b) {
    asm("mma.sync.aligned.m16n8k16.row.col.f32.bf16.bf16.f32 "
        "{%0,%1,%2,%3}, {%4,%5,%6,%7}, {%8,%9}, {%0,%1,%2,%3};"
        : "+f"(d[0]), "+f"(d[1]), "+f"(d[2]), "+f"(d[3])
        : "r"(a[0]), "r"(a[1]), "r"(a[2]), "r"(a[3]), "r"(b[0]), "r"(b[1]));
}
__device__ __forceinline__ void mma_f16(float* d, const uint32_t* a, const uint32_t* b) {
    asm("mma.sync.aligned.m16n8k16.row.col.f32.f16.f16.f32 "
        "{%0,%1,%2,%3}, {%4,%5,%6,%7}, {%8,%9}, {%0,%1,%2,%3};"
        : "+f"(d[0]), "+f"(d[1]), "+f"(d[2]), "+f"(d[3])
        : "r"(a[0]), "r"(a[1]), "r"(a[2]), "r"(a[3]), "r"(b[0]), "r"(b[1]));
}
__device__ __forceinline__ uint32_t packh2(float a, float b) {
    __half2 h = __floats2half2_rn(a, b);
    return *(uint32_t*)&h;
}
__device__ __forceinline__ uint32_t ex2h2(uint32_t in) {
    uint32_t r;
    asm("ex2.approx.f16x2 %0, %1;" : "=r"(r) : "r"(in));
    return r;
}
__device__ __forceinline__ void split2(float a, float b, uint32_t& hi, uint32_t& lo) {
    __nv_bfloat162 h2 = __floats2bfloat162_rn(a, b);
    float ar = a - __bfloat162float(h2.x);
    float br = b - __bfloat162float(h2.y);
    __nv_bfloat162 l2 = __floats2bfloat162_rn(ar, br);
    hi = *(uint32_t*)&h2;
    lo = *(uint32_t*)&l2;
}
__device__ __forceinline__ void split2h(float a, float b, uint32_t& hi, uint32_t& lo) {
    __half2 h2 = __floats2half2_rn(a, b);
    float ar = a - __half2float(__low2half(h2));
    float br = b - __half2float(__high2half(h2));
    __half2 l2 = __floats2half2_rn(ar, br);
    hi = *(uint32_t*)&h2;
    lo = *(uint32_t*)&l2;
}

#define CP_ASYNC16(dst, src) \
    asm volatile("cp.async.cg.shared.global [%0], [%1], 16;" :: "r"(dst), "l"(src) : "memory")
#define CP_COMMIT() asm volatile("cp.async.commit_group;" ::: "memory")
#define CP_WAIT1()  asm volatile("cp.async.wait_group 1;" ::: "memory")
#define CP_WAIT0()  asm volatile("cp.async.wait_group 0;" ::: "memory")
#define LDSM4T(d0, d1, d2, d3, a) \
    asm volatile("ldmatrix.sync.aligned.m8n8.x4.trans.shared.b16 {%0,%1,%2,%3}, [%4];" \
                 : "=r"(d0), "=r"(d1), "=r"(d2), "=r"(d3) : "r"(a))

// ---------------------------------------------------------------------------
// QKV via bf16 m16n8k16, 3-term split; W split inline (prep kernel removed).
// Writes q as fp32, k/v as packed fp16 (ready-to-use attn tile layout).
// ---------------------------------------------------------------------------
__global__ __launch_bounds__(256, 2)
void qkv_kernel(const float* __restrict__ x,
                const float* __restrict__ Wq, const float* __restrict__ Wk,
                const float* __restrict__ Wv,
                const float* __restrict__ bq, const float* __restrict__ bk,
                const float* __restrict__ bv)
{
    __shared__ uint32_t xs_h[64][20],  xs_l[64][20];
    __shared__ uint32_t ws_h[192][20], ws_l[192][20];

    const int t    = threadIdx.x;
    const int lane = t & 31;
    const int wid  = t >> 5;
    const int wm   = wid & 1;
    const int wn   = wid >> 1;
    const int gq   = lane >> 2;
    const int tg   = lane & 3;
    const size_t rowBase = (size_t)blockIdx.x * 64;

    float acc[2][6][4];
    #pragma unroll
    for (int mi = 0; mi < 2; mi++)
        #pragma unroll
        for (int ni = 0; ni < 6; ni++)
            #pragma unroll
            for (int j = 0; j < 4; j++) acc[mi][ni][j] = 0.f;

    const int xr = t >> 2;
    const int xc = (t & 3) * 8;
    const int wr0 = t >> 2;            // W loader row within 64-row band
    const int wcq = (t & 3);           // col quad

    for (int ch = 0; ch < 32; ch++) {
        __syncthreads();
        // x tile: split inline
        {
            const float* xp = x + (rowBase + xr) * ED + ch * 32 + xc;
            float4 f0 = *(const float4*)xp;
            float4 f1 = *(const float4*)(xp + 4);
            uint4 hv, lv;
            split2(f0.x, f0.y, hv.x, lv.x);
            split2(f0.z, f0.w, hv.y, lv.y);
            split2(f1.x, f1.y, hv.z, lv.z);
            split2(f1.z, f1.w, hv.w, lv.w);
            *(uint4*)&xs_h[xr][(t & 3) * 4] = hv;
            *(uint4*)&xs_l[xr][(t & 3) * 4] = lv;
        }
        // W tiles: fp32 load + inline split (i=0:Wq rows, 1:Wk, 2:Wv)
        #pragma unroll
        for (int i = 0; i < 3; i++) {
            const float* src = (i == 0) ? Wq : (i == 1) ? Wk : Wv;
            const float* wp = src + (size_t)wr0 * ED + ch * 32 + wcq * 8;
            float4 f0 = *(const float4*)wp;
            float4 f1 = *(const float4*)(wp + 4);
            uint4 hv, lv;
            split2(f0.x, f0.y, hv.x, lv.x);
            split2(f0.z, f0.w, hv.y, lv.y);
            split2(f1.x, f1.y, hv.z, lv.z);
            split2(f1.z, f1.w, hv.w, lv.w);
            int r = wr0 + i * 64;
            *(uint4*)&ws_h[r][wcq * 4] = hv;
            *(uint4*)&ws_l[r][wcq * 4] = lv;
        }
        __syncthreads();

        #pragma unroll
        for (int kk = 0; kk < 2; kk++) {
            const int c0 = kk * 8 + tg;
            uint32_t ah[2][4], al[2][4];
            #pragma unroll
            for (int mi = 0; mi < 2; mi++) {
                int r0 = wm * 32 + mi * 16 + gq;
                ah[mi][0] = xs_h[r0][c0];     ah[mi][1] = xs_h[r0 + 8][c0];
                ah[mi][2] = xs_h[r0][c0 + 4]; ah[mi][3] = xs_h[r0 + 8][c0 + 4];
                al[mi][0] = xs_l[r0][c0];     al[mi][1] = xs_l[r0 + 8][c0];
                al[mi][2] = xs_l[r0][c0 + 4]; al[mi][3] = xs_l[r0 + 8][c0 + 4];
            }
            uint32_t bh[6][2], bl[6][2];
            #pragma unroll
            for (int ni = 0; ni < 6; ni++) {
                int n0 = wn * 48 + ni * 8 + gq;
                bh[ni][0] = ws_h[n0][c0]; bh[ni][1] = ws_h[n0][c0 + 4];
                bl[ni][0] = ws_l[n0][c0]; bl[ni][1] = ws_l[n0][c0 + 4];
            }
            #pragma unroll
            for (int mi = 0; mi < 2; mi++)
                #pragma unroll
                for (int ni = 0; ni < 6; ni++) mma_bf16(acc[mi][ni], ah[mi], bh[ni]);
            #pragma unroll
            for (int mi = 0; mi < 2; mi++)
                #pragma unroll
                for (int ni = 0; ni < 6; ni++) mma_bf16(acc[mi][ni], ah[mi], bl[ni]);
            #pragma unroll
            for (int mi = 0; mi < 2; mi++)
                #pragma unroll
                for (int ni = 0; ni < 6; ni++) mma_bf16(acc[mi][ni], al[mi], bh[ni]);
        }
    }

    #pragma unroll
    for (int ni = 0; ni < 6; ni++) {
        const int gc0 = wn * 48 + ni * 8;
        const int wi  = gc0 >> 6;
        const int h0  = (gc0 & 63) + tg * 2;
        const float* bp = (wi == 0) ? bq : (wi == 1) ? bk : bv;
        const float b0 = bp[h0], b1 = bp[h0 + 1];
        #pragma unroll
        for (int mi = 0; mi < 2; mi++) {
            size_t r = rowBase + wm * 32 + mi * 16 + gq;
            if (wi == 0) {
                *(float2*)(g_q + r * HD + h0) =
                    make_float2(acc[mi][ni][0] + b0, acc[mi][ni][1] + b1);
                *(float2*)(g_q + (r + 8) * HD + h0) =
                    make_float2(acc[mi][ni][2] + b0, acc[mi][ni][3] + b1);
            } else {
                uint32_t* outp = (wi == 1) ? g_k16 : g_v16;
                int hp = ((gc0 & 63) >> 1) + tg;
                outp[r * 32 + hp]       = packh2(acc[mi][ni][0] + b0, acc[mi][ni][1] + b1);
                outp[(r + 8) * 32 + hp] = packh2(acc[mi][ni][2] + b0, acc[mi][ni][3] + b1);
            }
        }
    }
}

// ---------------------------------------------------------------------------
// Causal flash attention v6. 512 threads = 4 k-split groups x 4 warps,
// BK=64 tiles, cp.async double-buffered fp16 K/V (no cvt, no LDG stalls),
// V B-fragments via ldmatrix.x4.trans. ex2.f16x2 softmax, ones-MMA row sums.
// ---------------------------------------------------------------------------
#define GROUP_BAR(gid) asm volatile("bar.sync %0, 128;" :: "r"((gid) + 1) : "memory")
#define ATTN_SMEM (147456)

extern __shared__ uint32_t sbuf[];

__global__ __launch_bounds__(512, 1)
void attn_kernel(float* __restrict__ out)
{
    const int t    = threadIdx.x;
    const int lane = t & 31;
    const int wid  = t >> 5;
    const int g    = wid >> 2;
    const int qb   = wid & 3;
    const int gq   = lane >> 2;
    const int tg   = lane & 3;
    const int tl   = t & 127;
    const int b    = blockIdx.y;
    const size_t bOff  = (size_t)b * SEQ * HD;   // fp32 q
    const size_t bOffH = (size_t)b * SEQ * 32;   // packed fp16 k/v

    const uint32_t gbase = g * 9216;             // u32 offset: 2 buffers x 4608
    const uint32_t smem0 = (uint32_t)__cvta_generic_to_shared(sbuf);
    float* obuf = (float*)sbuf;                  // merge overlay [64][68]
    float* mlb  = (float*)(sbuf + 4352);

    // cp.async chunk mapping: 512 chunks of 16B per 64x64 fp16 tile, 4/thread
    // chunk idx -> row = idx>>3, c = idx&7; row stride 36 u32 (144B)
    // V ldmatrix lane offset (row_k within 16, h-half select)
    const uint32_t vlane = (uint32_t)(((lane & 7) + ((lane >> 3) & 1) * 8) * 144
                                      + (lane >> 4) * 16);

    const float SC2 = 0.18033688f;     // log2(e) / 8

    for (int pass = 0; pass < 2; pass++) {
        __syncthreads();
        const int qt = pass ? (31 - blockIdx.x) : blockIdx.x;
        const int qbase = qt * 64;
        const int r0l = qb * 16 + gq;

        // Q fragments (fp16 2-term split) with log2e/8 pre-folded
        uint32_t qh2[4][4], ql2[4][4];
        {
            const float* qp = g_q + bOff + (size_t)(qbase + r0l) * HD;
            #pragma unroll
            for (int c = 0; c < 4; c++) {
                int c0 = c * 16 + tg * 2;
                float2 f00 = *(const float2*)(qp + c0);
                float2 f10 = *(const float2*)(qp + 8 * HD + c0);
                float2 f01 = *(const float2*)(qp + c0 + 8);
                float2 f11 = *(const float2*)(qp + 8 * HD + c0 + 8);
                split2h(f00.x * SC2, f00.y * SC2, qh2[c][0], ql2[c][0]);
                split2h(f10.x * SC2, f10.y * SC2, qh2[c][1], ql2[c][1]);
                split2h(f01.x * SC2, f01.y * SC2, qh2[c][2], ql2[c][2]);
                split2h(f11.x * SC2, f11.y * SC2, qh2[c][3], ql2[c][3]);
            }
        }

        float m0 = -1e30f, m1 = -1e30f;
        float lacc[4] = {0.f, 0.f, 0.f, 0.f};
        float O[8][4];
        #pragma unroll
        for (int nh = 0; nh < 8; nh++)
            #pragma unroll
            for (int j = 0; j < 4; j++) O[nh][j] = 0.f;

        const int ng = (qt >= g) ? (((qt - g) >> 2) + 1) : 0;

        #define ISSUE_CP(KB, BUFI) do {                                           \
            uint32_t dstK = smem0 + (gbase + (BUFI) * 4608) * 4;                  \
            uint32_t dstV = dstK + 9216;                                          \
            _Pragma("unroll")                                                     \
            for (int i = 0; i < 4; i++) {                                         \
                int idx = tl + 128 * i;                                           \
                int row = idx >> 3, c = idx & 7;                                  \
                uint32_t so = (uint32_t)(row * 144 + c * 16);                     \
                const uint32_t* sk = g_k16 + bOffH + (size_t)((KB) + row) * 32 + c * 4; \
                const uint32_t* sv = g_v16 + bOffH + (size_t)((KB) + row) * 32 + c * 4; \
                CP_ASYNC16(dstK + so, sk);                                        \
                CP_ASYNC16(dstV + so, sv);                                        \
            }                                                                     \
            CP_COMMIT();                                                          \
        } while (0)

        if (ng > 0) ISSUE_CP(g * 64, 0);
        if (ng > 1) ISSUE_CP((4 + g) * 64, 1);

        for (int r = 0; r < ng; r++) {
            const int cur = r & 1;
            const int kbase = (4 * r + g) * 64;
            uint32_t* kst = sbuf + gbase + cur * 4608;
            const uint32_t vbytes = smem0 + (gbase + cur * 4608 + 2304) * 4;

            if (r + 1 < ng) CP_WAIT1(); else CP_WAIT0();
            GROUP_BAR(g);   // tile r visible group-wide

            // ---- S = Q K^T (pre-scaled by log2e/8) ----
            float s[8][4];
            #pragma unroll
            for (int nk = 0; nk < 8; nk++)
                #pragma unroll
                for (int j2 = 0; j2 < 4; j2++) s[nk][j2] = 0.f;

            #pragma unroll
            for (int c = 0; c < 4; c++) {
                uint32_t bfr[8][2];
                #pragma unroll
                for (int nk = 0; nk < 8; nk++) {
                    const uint32_t* kr = kst + (nk * 8 + gq) * 36 + c * 8 + tg;
                    bfr[nk][0] = kr[0];
                    bfr[nk][1] = kr[4];
                }
                #pragma unroll
                for (int nk = 0; nk < 8; nk++) mma_f16(s[nk], qh2[c], bfr[nk]);
                #pragma unroll
                for (int nk = 0; nk < 8; nk++) mma_f16(s[nk], ql2[c], bfr[nk]);
            }

            // ---- causal mask: only the diagonal tile ----
            if (kbase == qbase) {
                const int row0 = r0l, row1 = r0l + 8;
                #pragma unroll
                for (int nk = 0; nk < 8; nk++) {
                    int c = nk * 8 + tg * 2;
                    if (c     > row0) s[nk][0] = -1e30f;
                    if (c + 1 > row0) s[nk][1] = -1e30f;
                    if (c     > row1) s[nk][2] = -1e30f;
                    if (c + 1 > row1) s[nk][3] = -1e30f;
                }
            }

            // ---- online max ----
            float rm0 = -1e30f, rm1 = -1e30f;
            #pragma unroll
            for (int nk = 0; nk < 8; nk++) {
                rm0 = fmaxf(rm0, fmaxf(s[nk][0], s[nk][1]));
                rm1 = fmaxf(rm1, fmaxf(s[nk][2], s[nk][3]));
            }
            rm0 = fmaxf(rm0, __shfl_xor_sync(0xffffffffu, rm0, 1));
            rm0 = fmaxf(rm0, __shfl_xor_sync(0xffffffffu, rm0, 2));
            rm1 = fmaxf(rm1, __shfl_xor_sync(0xffffffffu, rm1, 1));
            rm1 = fmaxf(rm1, __shfl_xor_sync(0xffffffffu, rm1, 2));

            float mn0 = fmaxf(m0, rm0), mn1 = fmaxf(m1, rm1);
            float a0 = exp2f(m0 - mn0), a1 = exp2f(m1 - mn1);
            m0 = mn0; m1 = mn1;
            lacc[0] *= a0; lacc[1] *= a0; lacc[2] *= a1; lacc[3] *= a1;
            #pragma unroll
            for (int nh = 0; nh < 8; nh++) {
                O[nh][0] *= a0; O[nh][1] *= a0;
                O[nh][2] *= a1; O[nh][3] *= a1;
            }

            // ---- P = exp2(s-m) packed; O += P V (ldmatrix.trans); l via ones-MMA ----
            const uint32_t ones2[2] = {0x3C003C00u, 0x3C003C00u};
            #pragma unroll
            for (int c = 0; c < 4; c++) {
                uint32_t pa[4];
                pa[0] = ex2h2(packh2(s[2 * c][0]     - m0, s[2 * c][1]     - m0));
                pa[1] = ex2h2(packh2(s[2 * c][2]     - m1, s[2 * c][3]     - m1));
                pa[2] = ex2h2(packh2(s[2 * c + 1][0] - m0, s[2 * c + 1][1] - m0));
                pa[3] = ex2h2(packh2(s[2 * c + 1][2] - m1, s[2 * c + 1][3] - m1));
                #pragma unroll
                for (int hb = 0; hb < 4; hb++) {
                    uint32_t d0, d1, d2, d3;
                    uint32_t addr = vbytes + vlane + (uint32_t)(c * 16 * 144 + hb * 32);
                    LDSM4T(d0, d1, d2, d3, addr);
                    uint32_t vb0[2] = {d0, d1};
                    uint32_t vb1[2] = {d2, d3};
                    mma_f16(O[2 * hb],     pa, vb0);
                    mma_f16(O[2 * hb + 1], pa, vb1);
                }
                mma_f16(lacc, pa, ones2);
            }

            GROUP_BAR(g);   // all group warps done reading buf[cur]
            if (r + 2 < ng) ISSUE_CP((4 * (r + 2) + g) * 64, cur);
        }

        float l0 = lacc[0], l1 = lacc[2];

        // ---- 4-way merge: groups 1..3 feed group 0 ----
        __syncthreads();
        #pragma unroll
        for (int rr = 1; rr < 4; rr++) {
            if (g == rr) {
                mlb[r0l * 2]           = m0;
                mlb[r0l * 2 + 1]       = l0;
                mlb[(r0l + 8) * 2]     = m1;
                mlb[(r0l + 8) * 2 + 1] = l1;
                #pragma unroll
                for (int nh = 0; nh < 8; nh++) {
                    int c = nh * 8 + tg * 2;
                    *(float2*)&obuf[r0l * 68 + c]       = make_float2(O[nh][0], O[nh][1]);
                    *(float2*)&obuf[(r0l + 8) * 68 + c] = make_float2(O[nh][2], O[nh][3]);
                }
            }
            __syncthreads();
            if (g == 0) {
                float mb0 = mlb[r0l * 2],       lb0 = mlb[r0l * 2 + 1];
                float mb1 = mlb[(r0l + 8) * 2], lb1 = mlb[(r0l + 8) * 2 + 1];
                float M0 = fmaxf(m0, mb0), M1 = fmaxf(m1, mb1);
                float ea0 = exp2f(m0 - M0),  eb0 = exp2f(mb0 - M0);
                float ea1 = exp2f(m1 - M1),  eb1 = exp2f(mb1 - M1);
                l0 = l0 * ea0 + lb0 * eb0;
                l1 = l1 * ea1 + lb1 * eb1;
                m0 = M0; m1 = M1;
                #pragma unroll
                for (int nh = 0; nh < 8; nh++) {
                    int c = nh * 8 + tg * 2;
                    float2 ob0 = *(float2*)&obuf[r0l * 68 + c];
                    float2 ob1 = *(float2*)&obuf[(r0l + 8) * 68 + c];
                    O[nh][0] = O[nh][0] * ea0 + ob0.x * eb0;
                    O[nh][1] = O[nh][1] * ea0 + ob0.y * eb0;
                    O[nh][2] = O[nh][2] * ea1 + ob1.x * eb1;
                    O[nh][3] = O[nh][3] * ea1 + ob1.y * eb1;
                }
            }
            __syncthreads();
        }

        if (g == 0) {
            const float inv0 = 1.f / l0, inv1 = 1.f / l1;
            const int r = qbase + r0l;
            #pragma unroll
            for (int nh = 0; nh < 8; nh++) {
                int c = nh * 8 + tg * 2;
                *(float2*)(out + bOff + (size_t)r * HD + c) =
                    make_float2(O[nh][0] * inv0, O[nh][1] * inv0);
                *(float2*)(out + bOff + (size_t)(r + 8) * HD + c) =
                    make_float2(O[nh][2] * inv1, O[nh][3] * inv1);
            }
        }
        #undef ISSUE_CP
    }
}

// ---------------------------------------------------------------------------
extern "C" void kernel_launch(void* const* d_in, const int* in_sizes, int n_in,
                              void* d_out, int out_size)
{
    const float* x  = (const float*)d_in[0];
    const float* Wq = (const float*)d_in[1];
    const float* bq = (const float*)d_in[2];
    const float* Wk = (const float*)d_in[3];
    const float* bk = (const float*)d_in[4];
    const float* Wv = (const float*)d_in[5];
    const float* bv = (const float*)d_in[6];
    float* out = (float*)d_out;

    cudaFuncSetAttribute(attn_kernel, cudaFuncAttributeMaxDynamicSharedMemorySize, ATTN_SMEM);

    qkv_kernel<<<(NB * SEQ) / 64, 256>>>(x, Wq, Wk, Wv, bq, bk, bv);
    attn_kernel<<<dim3(16, NB), 512, ATTN_SMEM>>>(out);
}